// round 9
// baseline (speedup 1.0000x reference)
#include <cuda_runtime.h>

#define NN 50000
#define EE 800000
#define FULL 0xffffffffu

// ---------------- scratch (static device globals; no allocs) ----------------
static __device__ float g_h[NN*64];      // GCN-transformed features
static __device__ float g_res[NN*64];    // residual branch
static __device__ float g_xln[NN*64];    // post-GCN layernorm output
static __device__ float g_xg[NN*64];     // GAT-transformed features
static __device__ float g_xcur[NN*64];   // layer-0 output
static __device__ float g_deg[NN];
static __device__ float g_dinv[NN];
static __device__ int   g_cnt[NN];       // in-degree counts (edges only)
static __device__ int   g_ps[NN];        // inclusive scan scratch
static __device__ int   g_blk[128];      // block sums
static __device__ int   g_blkoff[128];
static __device__ int   g_rowptr[NN+1];
static __device__ int   g_cur[NN];
static __device__ int2  g_cpk[EE];       // CSR slot -> (src, gcn-weight bits)
static __device__ int   g_cdst[EE];      // CSR dst node per slot
static __device__ float g_cea[EE];       // CSR edge_attr per slot
static __device__ float g_as[NN*4];
static __device__ float g_ad[NN*4];
static __device__ float g_ep[EE*4];      // exp(alpha) per CSR slot, 4 heads
static __device__ float g_ce[8];         // [0..3]=ce per head, [4]=mean(edge_attr)
static __device__ float g_easum;

// ---------------- helpers ----------------
__device__ __forceinline__ float siluf(float v) { return v * (1.f / (1.f + __expf(-v))); }
__device__ __forceinline__ float lrelu(float v) { return v >= 0.f ? v : 0.2f * v; }

// ---------------- GEMMs ----------------
// g_h = x@W0, g_res = x@W1 + b1. 32-row tile, 256 threads.
__global__ __launch_bounds__(256) void k_gemm_dual(
    const float* __restrict__ xin, const float* __restrict__ W0,
    const float* __restrict__ W1, const float* __restrict__ b1)
{
    const float* x = xin ? xin : g_xcur;
    __shared__ float xs[32*68];
    __shared__ float ws[2][64*68];
    int t = threadIdx.x;
    int row0 = blockIdx.x * 32;
    for (int i = t; i < 4096; i += 256) {
        int k = i >> 6, c = i & 63;
        ws[0][k*68+c] = W0[i];
        ws[1][k*68+c] = W1[i];
    }
    for (int i = t; i < 2048; i += 256) {
        int r = i >> 6, c = i & 63;
        xs[r*68+c] = (row0 + r < NN) ? x[(row0+r)*64 + c] : 0.f;
    }
    __syncthreads();
    int rg = t >> 4, g = t & 15, m = g >> 3, cb = (g & 7) * 8;
    const float* wp = ws[m];
    int r0 = rg*2, r1 = r0 + 1;
    float a0[8], a1[8];
    #pragma unroll
    for (int j = 0; j < 8; j++) { a0[j] = 0.f; a1[j] = 0.f; }
    #pragma unroll 16
    for (int k = 0; k < 64; k++) {
        float xv0 = xs[r0*68+k], xv1 = xs[r1*68+k];
        float w[8];
        *(float4*)&w[0] = *(const float4*)&wp[k*68+cb];
        *(float4*)&w[4] = *(const float4*)&wp[k*68+cb+4];
        #pragma unroll
        for (int j = 0; j < 8; j++) { a0[j] += xv0 * w[j]; a1[j] += xv1 * w[j]; }
    }
    float* y = m ? g_res : g_h;
    if (m) {
        #pragma unroll
        for (int j = 0; j < 8; j++) { float b = b1[cb+j]; a0[j] += b; a1[j] += b; }
    }
    if (row0 + r0 < NN) {
        *(float4*)&y[(row0+r0)*64+cb]   = *(float4*)&a0[0];
        *(float4*)&y[(row0+r0)*64+cb+4] = *(float4*)&a0[4];
    }
    if (row0 + r1 < NN) {
        *(float4*)&y[(row0+r1)*64+cb]   = *(float4*)&a1[0];
        *(float4*)&y[(row0+r1)*64+cb+4] = *(float4*)&a1[4];
    }
}

// g_xg = g_xln @ W ; fused attention dots g_as/g_ad. 64-row tile, 256 threads.
__global__ __launch_bounds__(256) void k_gemm_gat(
    const float* __restrict__ W,
    const float* __restrict__ asrc, const float* __restrict__ adst)
{
    __shared__ float xs[64*68];
    __shared__ float ws[64*68];
    int t = threadIdx.x;
    int row0 = blockIdx.x * 64;
    for (int i = t; i < 4096; i += 256) {
        int k = i >> 6, c = i & 63;
        ws[k*68+c] = W[i];
    }
    for (int i = t; i < 4096; i += 256) {
        int r = i >> 6, c = i & 63;
        xs[r*68+c] = (row0 + r < NN) ? g_xln[(row0+r)*64 + c] : 0.f;
    }
    __syncthreads();
    int rg = t >> 3, cb = (t & 7) * 8;
    int r0 = rg*2, r1 = r0 + 1;
    float a0[8], a1[8];
    #pragma unroll
    for (int j = 0; j < 8; j++) { a0[j] = 0.f; a1[j] = 0.f; }
    #pragma unroll 16
    for (int k = 0; k < 64; k++) {
        float xv0 = xs[r0*68+k], xv1 = xs[r1*68+k];
        float w[8];
        *(float4*)&w[0] = *(const float4*)&ws[k*68+cb];
        *(float4*)&w[4] = *(const float4*)&ws[k*68+cb+4];
        #pragma unroll
        for (int j = 0; j < 8; j++) { a0[j] += xv0 * w[j]; a1[j] += xv1 * w[j]; }
    }
    if (row0 + r0 < NN) {
        *(float4*)&g_xg[(row0+r0)*64+cb]   = *(float4*)&a0[0];
        *(float4*)&g_xg[(row0+r0)*64+cb+4] = *(float4*)&a0[4];
    }
    if (row0 + r1 < NN) {
        *(float4*)&g_xg[(row0+r1)*64+cb]   = *(float4*)&a1[0];
        *(float4*)&g_xg[(row0+r1)*64+cb+4] = *(float4*)&a1[4];
    }
    // fused attention dots: thread pair (t, t^1) covers one head (16 cols)
    float s0 = 0.f, s1 = 0.f, d0 = 0.f, d1 = 0.f;
    #pragma unroll
    for (int j = 0; j < 8; j++) {
        float av = asrc[cb+j], dv = adst[cb+j];
        s0 += a0[j]*av; d0 += a0[j]*dv;
        s1 += a1[j]*av; d1 += a1[j]*dv;
    }
    s0 += __shfl_xor_sync(FULL, s0, 1);
    s1 += __shfl_xor_sync(FULL, s1, 1);
    d0 += __shfl_xor_sync(FULL, d0, 1);
    d1 += __shfl_xor_sync(FULL, d1, 1);
    if ((t & 1) == 0) {
        int hh = cb >> 4;
        if (row0 + r0 < NN) { g_as[(row0+r0)*4+hh] = s0; g_ad[(row0+r0)*4+hh] = d0; }
        if (row0 + r1 < NN) { g_as[(row0+r1)*4+hh] = s1; g_ad[(row0+r1)*4+hh] = d1; }
    }
}

// ---------------- graph setup (once per call) ----------------
__global__ void k_init() {
    int i = blockIdx.x*256 + threadIdx.x;
    if (i < NN) { g_deg[i] = 1.f; g_cnt[i] = 0; }
    if (i == 0) g_easum = 0.f;
}
// deg/cnt accumulation + edge_attr sum (warp-reduced)
__global__ void k_deg_edge(const int* __restrict__ ei, const float* __restrict__ ew,
                           const float* __restrict__ ea) {
    int e = blockIdx.x*256 + threadIdx.x;
    int d = ei[EE+e];
    atomicAdd(&g_deg[d], ew[e]);
    atomicAdd(&g_cnt[d], 1);
    float v = ea[e];
    #pragma unroll
    for (int o = 16; o; o >>= 1) v += __shfl_xor_sync(FULL, v, o);
    if ((threadIdx.x & 31) == 0) atomicAdd(&g_easum, v);
}
__global__ __launch_bounds__(512) void k_scan1() {
    __shared__ int sm[512];
    int t = threadIdx.x;
    int idx = blockIdx.x*512 + t;
    if (idx < NN) g_dinv[idx] = rsqrtf(g_deg[idx]);
    int c = (idx < NN) ? g_cnt[idx] : 0;
    sm[t] = c; __syncthreads();
    #pragma unroll
    for (int off = 1; off < 512; off <<= 1) {
        int v = (t >= off) ? sm[t-off] : 0;
        __syncthreads();
        sm[t] += v;
        __syncthreads();
    }
    if (idx < NN) g_ps[idx] = sm[t];
    if (t == 511) g_blk[blockIdx.x] = sm[511];
}
__global__ void k_scan2(int nblk) {
    if (threadIdx.x == 0) {
        int run = 0;
        for (int i = 0; i < nblk; i++) { g_blkoff[i] = run; run += g_blk[i]; }
    }
}
__global__ __launch_bounds__(512) void k_scan3() {
    int idx = blockIdx.x*512 + threadIdx.x;
    if (idx < NN) {
        g_rowptr[idx+1] = g_ps[idx] + g_blkoff[blockIdx.x];
        g_cur[idx] = 0;
        if (idx == 0) g_rowptr[0] = 0;
    }
}
__global__ void k_fill(const int* __restrict__ ei, const float* __restrict__ ew,
                       const float* __restrict__ ea) {
    int e = blockIdx.x*256 + threadIdx.x;
    int s = ei[e], d = ei[EE+e];
    int pos = g_rowptr[d] + atomicAdd(&g_cur[d], 1);
    g_cpk[pos] = make_int2(s, __float_as_int(g_dinv[s] * ew[e] * g_dinv[d]));
    g_cdst[pos] = d;
    g_cea[pos]  = ea[e];
}

// -------- GCN gather + silu + residual + LN (warp per node, quarter-warp per edge) --
__global__ __launch_bounds__(256) void k_gcn_ln(
    const float* __restrict__ gb, const float* __restrict__ lg, const float* __restrict__ lb)
{
    int row = blockIdx.x*8 + (threadIdx.x >> 5);
    if (row >= NN) return;
    int lane = threadIdx.x & 31;
    int q = lane & 7, quarter = lane >> 3;   // q: 8-col group, quarter: edge slot
    int start = g_rowptr[row], end = g_rowptr[row+1];
    float4 aA = make_float4(0.f,0.f,0.f,0.f);
    float4 aB = make_float4(0.f,0.f,0.f,0.f);
    if (quarter == 0) {
        float dv = g_dinv[row];
        float ss = dv * dv;
        float4 h0 = *(const float4*)&g_h[row*64 + q*8];
        float4 h1 = *(const float4*)&g_h[row*64 + q*8 + 4];
        aA.x = h0.x*ss; aA.y = h0.y*ss; aA.z = h0.z*ss; aA.w = h0.w*ss;
        aB.x = h1.x*ss; aB.y = h1.y*ss; aB.z = h1.z*ss; aB.w = h1.w*ss;
    }
    for (int j = start + quarter; j < end; j += 4) {
        int2 pk = __ldg(&g_cpk[j]);
        float w = __int_as_float(pk.y);
        const float* hp = &g_h[pk.x*64 + q*8];
        float4 v0 = *(const float4*)hp;
        float4 v1 = *(const float4*)(hp + 4);
        aA.x += w*v0.x; aA.y += w*v0.y; aA.z += w*v0.z; aA.w += w*v0.w;
        aB.x += w*v1.x; aB.y += w*v1.y; aB.z += w*v1.z; aB.w += w*v1.w;
    }
    // combine across quarters (xor 8, 16)
    #pragma unroll
    for (int o = 8; o <= 16; o <<= 1) {
        aA.x += __shfl_xor_sync(FULL, aA.x, o);
        aA.y += __shfl_xor_sync(FULL, aA.y, o);
        aA.z += __shfl_xor_sync(FULL, aA.z, o);
        aA.w += __shfl_xor_sync(FULL, aA.w, o);
        aB.x += __shfl_xor_sync(FULL, aB.x, o);
        aB.y += __shfl_xor_sync(FULL, aB.y, o);
        aB.z += __shfl_xor_sync(FULL, aB.z, o);
        aB.w += __shfl_xor_sync(FULL, aB.w, o);
    }
    // silu + residual (redundant across quarters)
    float4 g0 = *(const float4*)&gb[q*8];
    float4 g1 = *(const float4*)&gb[q*8 + 4];
    float4 r0 = *(const float4*)&g_res[row*64 + q*8];
    float4 r1 = *(const float4*)&g_res[row*64 + q*8 + 4];
    float4 vA, vB;
    vA.x = siluf(aA.x + g0.x) + r0.x;
    vA.y = siluf(aA.y + g0.y) + r0.y;
    vA.z = siluf(aA.z + g0.z) + r0.z;
    vA.w = siluf(aA.w + g0.w) + r0.w;
    vB.x = siluf(aB.x + g1.x) + r1.x;
    vB.y = siluf(aB.y + g1.y) + r1.y;
    vB.z = siluf(aB.z + g1.z) + r1.z;
    vB.w = siluf(aB.w + g1.w) + r1.w;
    float sum = vA.x+vA.y+vA.z+vA.w + vB.x+vB.y+vB.z+vB.w;
    #pragma unroll
    for (int o = 4; o; o >>= 1) sum += __shfl_xor_sync(FULL, sum, o);
    float mu = sum * (1.f/64.f);
    float4 dA, dB;
    dA.x = vA.x-mu; dA.y = vA.y-mu; dA.z = vA.z-mu; dA.w = vA.w-mu;
    dB.x = vB.x-mu; dB.y = vB.y-mu; dB.z = vB.z-mu; dB.w = vB.w-mu;
    float vs = dA.x*dA.x+dA.y*dA.y+dA.z*dA.z+dA.w*dA.w
             + dB.x*dB.x+dB.y*dB.y+dB.z*dB.z+dB.w*dB.w;
    #pragma unroll
    for (int o = 4; o; o >>= 1) vs += __shfl_xor_sync(FULL, vs, o);
    float inv = rsqrtf(vs * (1.f/64.f) + 1e-5f);
    if (quarter == 0) {
        float4 lgA = *(const float4*)&lg[q*8];
        float4 lgB = *(const float4*)&lg[q*8 + 4];
        float4 lbA = *(const float4*)&lb[q*8];
        float4 lbB = *(const float4*)&lb[q*8 + 4];
        float4 oA, oB;
        oA.x = dA.x*inv*lgA.x + lbA.x;
        oA.y = dA.y*inv*lgA.y + lbA.y;
        oA.z = dA.z*inv*lgA.z + lbA.z;
        oA.w = dA.w*inv*lgA.w + lbA.w;
        oB.x = dB.x*inv*lgB.x + lbB.x;
        oB.y = dB.y*inv*lgB.y + lbB.y;
        oB.z = dB.z*inv*lgB.z + lbB.z;
        oB.w = dB.w*inv*lgB.w + lbB.w;
        *(float4*)&g_xln[row*64 + q*8]     = oA;
        *(float4*)&g_xln[row*64 + q*8 + 4] = oB;
    }
}

// ---------------- GAT ----------------
// ce[h] = sum_c We[h*16+c]*a_e[h*16+c]; ce[4] = mean(edge_attr)
__global__ void k_ce(const float* __restrict__ eww, const float* __restrict__ ae) {
    int lane = threadIdx.x;
    float p0 = eww[lane]*ae[lane];
    float p1 = eww[lane+32]*ae[lane+32];
    #pragma unroll
    for (int o = 8; o; o >>= 1) {
        p0 += __shfl_xor_sync(FULL, p0, o);
        p1 += __shfl_xor_sync(FULL, p1, o);
    }
    if ((lane & 15) == 0) {
        g_ce[lane >> 4]       = p0;
        g_ce[2 + (lane >> 4)] = p1;
    }
    if (lane == 0) g_ce[4] = g_easum * (1.f / EE);
}
// CSR-ordered edge-parallel: exp(alpha) written linearly
__global__ void k_gatA() {
    int e = blockIdx.x*256 + threadIdx.x;   // CSR slot
    int s = g_cpk[e].x, d = g_cdst[e];
    float eav = g_cea[e];
    float4 av = *(const float4*)&g_as[s*4];
    float4 dv = *(const float4*)&g_ad[d*4];
    float4 ce = *(const float4*)&g_ce[0];
    float4 p;
    p.x = __expf(fminf(lrelu(av.x + dv.x + eav*ce.x), 70.f));
    p.y = __expf(fminf(lrelu(av.y + dv.y + eav*ce.y), 70.f));
    p.z = __expf(fminf(lrelu(av.z + dv.z + eav*ce.z), 70.f));
    p.w = __expf(fminf(lrelu(av.w + dv.w + eav*ce.w), 70.f));
    *(float4*)&g_ep[e*4] = p;
}
// warp-per-node, quarter-warp per edge: gather + inline softmax denom + silu + skip
__global__ __launch_bounds__(256) void k_gat_gather(
    const float* __restrict__ bg, float* __restrict__ xout)
{
    int row = blockIdx.x*8 + (threadIdx.x >> 5);
    if (row >= NN) return;
    int lane = threadIdx.x & 31;
    int q = lane & 7, quarter = lane >> 3;
    int h = q >> 1;                          // head of this lane's 8 columns
    int start = g_rowptr[row], end = g_rowptr[row+1];
    // self-loop exp(alpha)
    float4 av = *(const float4*)&g_as[row*4];
    float4 dv = *(const float4*)&g_ad[row*4];
    float4 ce = *(const float4*)&g_ce[0];
    float cm = g_ce[4];
    float4 ps;
    ps.x = __expf(fminf(lrelu(av.x + dv.x + cm*ce.x), 70.f));
    ps.y = __expf(fminf(lrelu(av.y + dv.y + cm*ce.y), 70.f));
    ps.z = __expf(fminf(lrelu(av.z + dv.z + cm*ce.z), 70.f));
    ps.w = __expf(fminf(lrelu(av.w + dv.w + cm*ce.w), 70.f));
    float p_self = (h == 0) ? ps.x : (h == 1) ? ps.y : (h == 2) ? ps.z : ps.w;
    float4 aA = make_float4(0.f,0.f,0.f,0.f);
    float4 aB = make_float4(0.f,0.f,0.f,0.f);
    float sa = 0.f;
    if (quarter == 0) {
        float4 x0 = *(const float4*)&g_xg[row*64 + q*8];
        float4 x1 = *(const float4*)&g_xg[row*64 + q*8 + 4];
        aA.x = x0.x*p_self; aA.y = x0.y*p_self; aA.z = x0.z*p_self; aA.w = x0.w*p_self;
        aB.x = x1.x*p_self; aB.y = x1.y*p_self; aB.z = x1.z*p_self; aB.w = x1.w*p_self;
        sa = p_self;
    }
    for (int j = start + quarter; j < end; j += 4) {
        int s = __ldg(&g_cpk[j]).x;
        float p = __ldg(&g_ep[j*4 + h]);
        const float* xp = &g_xg[s*64 + q*8];
        float4 v0 = *(const float4*)xp;
        float4 v1 = *(const float4*)(xp + 4);
        aA.x += p*v0.x; aA.y += p*v0.y; aA.z += p*v0.z; aA.w += p*v0.w;
        aB.x += p*v1.x; aB.y += p*v1.y; aB.z += p*v1.z; aB.w += p*v1.w;
        sa += p;
    }
    #pragma unroll
    for (int o = 8; o <= 16; o <<= 1) {
        aA.x += __shfl_xor_sync(FULL, aA.x, o);
        aA.y += __shfl_xor_sync(FULL, aA.y, o);
        aA.z += __shfl_xor_sync(FULL, aA.z, o);
        aA.w += __shfl_xor_sync(FULL, aA.w, o);
        aB.x += __shfl_xor_sync(FULL, aB.x, o);
        aB.y += __shfl_xor_sync(FULL, aB.y, o);
        aB.z += __shfl_xor_sync(FULL, aB.z, o);
        aB.w += __shfl_xor_sync(FULL, aB.w, o);
        sa   += __shfl_xor_sync(FULL, sa, o);
    }
    if (quarter == 0) {
        float ia = 1.f / (sa + 1e-16f);
        float4 b0 = *(const float4*)&bg[q*8];
        float4 b1 = *(const float4*)&bg[q*8 + 4];
        float4 x0 = *(const float4*)&g_xln[row*64 + q*8];
        float4 x1 = *(const float4*)&g_xln[row*64 + q*8 + 4];
        float* o = xout ? xout : g_xcur;
        float4 oA, oB;
        oA.x = siluf(aA.x*ia + b0.x) + x0.x;
        oA.y = siluf(aA.y*ia + b0.y) + x0.y;
        oA.z = siluf(aA.z*ia + b0.z) + x0.z;
        oA.w = siluf(aA.w*ia + b0.w) + x0.w;
        oB.x = siluf(aB.x*ia + b1.x) + x1.x;
        oB.y = siluf(aB.y*ia + b1.y) + x1.y;
        oB.z = siluf(aB.z*ia + b1.z) + x1.z;
        oB.w = siluf(aB.w*ia + b1.w) + x1.w;
        *(float4*)&o[row*64 + q*8]     = oA;
        *(float4*)&o[row*64 + q*8 + 4] = oB;
    }
}

// ---------------- launch ----------------
extern "C" void kernel_launch(void* const* d_in, const int* in_sizes, int n_in,
                              void* d_out, int out_size) {
    (void)in_sizes; (void)n_in; (void)out_size;
    const float* x  = (const float*)d_in[0];
    const int*   ei = (const int*)  d_in[1];
    const float* ew = (const float*)d_in[2];
    const float* ea = (const float*)d_in[3];

    // graph-structure setup (layer-independent)
    k_init<<<196,256>>>();
    k_deg_edge<<<3125,256>>>(ei, ew, ea);
    k_scan1<<<98,512>>>();
    k_scan2<<<1,32>>>(98);
    k_scan3<<<98,512>>>();
    k_fill<<<3125,256>>>(ei, ew, ea);

    for (int L = 0; L < 2; L++) {
        const float* gw  = (const float*)d_in[4+12*L+0];
        const float* gb  = (const float*)d_in[4+12*L+1];
        const float* rw  = (const float*)d_in[4+12*L+2];
        const float* rb  = (const float*)d_in[4+12*L+3];
        const float* lg  = (const float*)d_in[4+12*L+4];
        const float* lb  = (const float*)d_in[4+12*L+5];
        const float* Wg  = (const float*)d_in[4+12*L+6];
        const float* bg  = (const float*)d_in[4+12*L+7];
        const float* asv = (const float*)d_in[4+12*L+8];
        const float* adv = (const float*)d_in[4+12*L+9];
        const float* aev = (const float*)d_in[4+12*L+10];
        const float* eww = (const float*)d_in[4+12*L+11];

        const float* xin  = (L == 0) ? x : nullptr;             // null -> g_xcur
        float*       xout = (L == 1) ? (float*)d_out : nullptr; // null -> g_xcur

        k_gemm_dual<<<1563,256>>>(xin, gw, rw, rb);
        k_gcn_ln<<<6250,256>>>(gb, lg, lb);
        k_gemm_gat<<<782,256>>>(Wg, asv, adv);
        k_ce<<<1,32>>>(eww, aev);
        k_gatA<<<3125,256>>>();
        k_gat_gather<<<6250,256>>>(bg, xout);
    }
}

// round 11
// speedup vs baseline: 1.0882x; 1.0882x over previous
#include <cuda_runtime.h>

#define NN 50000
#define EE 800000
#define FULL 0xffffffffu

// ---------------- scratch (static device globals; no allocs) ----------------
static __device__ float g_h[NN*64];      // GCN-transformed features
static __device__ float g_res[NN*64];    // residual branch
static __device__ float g_xln[NN*64];    // post-GCN layernorm output
static __device__ float g_xg[NN*64];     // GAT-transformed features
static __device__ float g_xcur[NN*64];   // layer-0 output
static __device__ float g_deg[NN];
static __device__ float g_dinv[NN];
static __device__ int   g_cnt[NN];       // in-degree counts (edges only)
static __device__ int   g_ps[NN];        // inclusive scan scratch
static __device__ int   g_blk[128];      // block sums
static __device__ int   g_blkoff[128];
static __device__ int   g_rowptr[NN+1];
static __device__ int   g_cur[NN];
static __device__ int2  g_cpk[EE];       // CSR slot -> (src, gcn-weight bits)
static __device__ int   g_cdst[EE];      // CSR dst node per slot
static __device__ float g_cea[EE];       // CSR edge_attr per slot
static __device__ float g_as[NN*4];
static __device__ float g_ad[NN*4];
static __device__ float g_ep[EE*4];      // exp(alpha) per CSR slot, 4 heads
static __device__ float g_ce[8];         // [0..3]=ce per head, [4]=mean(edge_attr)
static __device__ float g_easum;

// ---------------- helpers ----------------
__device__ __forceinline__ float siluf(float v) { return v * (1.f / (1.f + __expf(-v))); }
__device__ __forceinline__ float lrelu(float v) { return v >= 0.f ? v : 0.2f * v; }

// ---------------- GEMMs ----------------
// g_h = x@W0, g_res = x@W1 + b1. 32-row tile, 256 threads.
__global__ __launch_bounds__(256) void k_gemm_dual(
    const float* __restrict__ xin, const float* __restrict__ W0,
    const float* __restrict__ W1, const float* __restrict__ b1)
{
    const float* x = xin ? xin : g_xcur;
    __shared__ float xs[32*68];
    __shared__ float ws[2][64*68];
    int t = threadIdx.x;
    int row0 = blockIdx.x * 32;
    for (int i = t; i < 4096; i += 256) {
        int k = i >> 6, c = i & 63;
        ws[0][k*68+c] = W0[i];
        ws[1][k*68+c] = W1[i];
    }
    for (int i = t; i < 2048; i += 256) {
        int r = i >> 6, c = i & 63;
        xs[r*68+c] = (row0 + r < NN) ? x[(row0+r)*64 + c] : 0.f;
    }
    __syncthreads();
    int rg = t >> 4, g = t & 15, m = g >> 3, cb = (g & 7) * 8;
    const float* wp = ws[m];
    int r0 = rg*2, r1 = r0 + 1;
    float a0[8], a1[8];
    #pragma unroll
    for (int j = 0; j < 8; j++) { a0[j] = 0.f; a1[j] = 0.f; }
    #pragma unroll 16
    for (int k = 0; k < 64; k++) {
        float xv0 = xs[r0*68+k], xv1 = xs[r1*68+k];
        float w[8];
        *(float4*)&w[0] = *(const float4*)&wp[k*68+cb];
        *(float4*)&w[4] = *(const float4*)&wp[k*68+cb+4];
        #pragma unroll
        for (int j = 0; j < 8; j++) { a0[j] += xv0 * w[j]; a1[j] += xv1 * w[j]; }
    }
    float* y = m ? g_res : g_h;
    if (m) {
        #pragma unroll
        for (int j = 0; j < 8; j++) { float b = b1[cb+j]; a0[j] += b; a1[j] += b; }
    }
    if (row0 + r0 < NN) {
        *(float4*)&y[(row0+r0)*64+cb]   = *(float4*)&a0[0];
        *(float4*)&y[(row0+r0)*64+cb+4] = *(float4*)&a0[4];
    }
    if (row0 + r1 < NN) {
        *(float4*)&y[(row0+r1)*64+cb]   = *(float4*)&a1[0];
        *(float4*)&y[(row0+r1)*64+cb+4] = *(float4*)&a1[4];
    }
}

// g_xg = g_xln @ W ; fused attention dots g_as/g_ad. 64-row tile, 256 threads.
__global__ __launch_bounds__(256) void k_gemm_gat(
    const float* __restrict__ W,
    const float* __restrict__ asrc, const float* __restrict__ adst)
{
    __shared__ float xs[64*68];
    __shared__ float ws[64*68];
    int t = threadIdx.x;
    int row0 = blockIdx.x * 64;
    for (int i = t; i < 4096; i += 256) {
        int k = i >> 6, c = i & 63;
        ws[k*68+c] = W[i];
    }
    for (int i = t; i < 4096; i += 256) {
        int r = i >> 6, c = i & 63;
        xs[r*68+c] = (row0 + r < NN) ? g_xln[(row0+r)*64 + c] : 0.f;
    }
    __syncthreads();
    int rg = t >> 3, cb = (t & 7) * 8;
    int r0 = rg*2, r1 = r0 + 1;
    float a0[8], a1[8];
    #pragma unroll
    for (int j = 0; j < 8; j++) { a0[j] = 0.f; a1[j] = 0.f; }
    #pragma unroll 16
    for (int k = 0; k < 64; k++) {
        float xv0 = xs[r0*68+k], xv1 = xs[r1*68+k];
        float w[8];
        *(float4*)&w[0] = *(const float4*)&ws[k*68+cb];
        *(float4*)&w[4] = *(const float4*)&ws[k*68+cb+4];
        #pragma unroll
        for (int j = 0; j < 8; j++) { a0[j] += xv0 * w[j]; a1[j] += xv1 * w[j]; }
    }
    if (row0 + r0 < NN) {
        *(float4*)&g_xg[(row0+r0)*64+cb]   = *(float4*)&a0[0];
        *(float4*)&g_xg[(row0+r0)*64+cb+4] = *(float4*)&a0[4];
    }
    if (row0 + r1 < NN) {
        *(float4*)&g_xg[(row0+r1)*64+cb]   = *(float4*)&a1[0];
        *(float4*)&g_xg[(row0+r1)*64+cb+4] = *(float4*)&a1[4];
    }
    // fused attention dots: thread pair (t, t^1) covers one head (16 cols)
    float s0 = 0.f, s1 = 0.f, d0 = 0.f, d1 = 0.f;
    #pragma unroll
    for (int j = 0; j < 8; j++) {
        float av = asrc[cb+j], dv = adst[cb+j];
        s0 += a0[j]*av; d0 += a0[j]*dv;
        s1 += a1[j]*av; d1 += a1[j]*dv;
    }
    s0 += __shfl_xor_sync(FULL, s0, 1);
    s1 += __shfl_xor_sync(FULL, s1, 1);
    d0 += __shfl_xor_sync(FULL, d0, 1);
    d1 += __shfl_xor_sync(FULL, d1, 1);
    if ((t & 1) == 0) {
        int hh = cb >> 4;
        if (row0 + r0 < NN) { g_as[(row0+r0)*4+hh] = s0; g_ad[(row0+r0)*4+hh] = d0; }
        if (row0 + r1 < NN) { g_as[(row0+r1)*4+hh] = s1; g_ad[(row0+r1)*4+hh] = d1; }
    }
}

// ---------------- graph setup (once per call) ----------------
__global__ void k_init() {
    int i = blockIdx.x*256 + threadIdx.x;
    if (i < NN) { g_deg[i] = 1.f; g_cnt[i] = 0; }
    if (i == 0) g_easum = 0.f;
}
// deg/cnt accumulation + edge_attr sum (warp-reduced)
__global__ void k_deg_edge(const int* __restrict__ ei, const float* __restrict__ ew,
                           const float* __restrict__ ea) {
    int e = blockIdx.x*256 + threadIdx.x;
    int d = ei[EE+e];
    atomicAdd(&g_deg[d], ew[e]);
    atomicAdd(&g_cnt[d], 1);
    float v = ea[e];
    #pragma unroll
    for (int o = 16; o; o >>= 1) v += __shfl_xor_sync(FULL, v, o);
    if ((threadIdx.x & 31) == 0) atomicAdd(&g_easum, v);
}
__global__ __launch_bounds__(512) void k_scan1() {
    __shared__ int sm[512];
    int t = threadIdx.x;
    int idx = blockIdx.x*512 + t;
    if (idx < NN) g_dinv[idx] = rsqrtf(g_deg[idx]);
    int c = (idx < NN) ? g_cnt[idx] : 0;
    sm[t] = c; __syncthreads();
    #pragma unroll
    for (int off = 1; off < 512; off <<= 1) {
        int v = (t >= off) ? sm[t-off] : 0;
        __syncthreads();
        sm[t] += v;
        __syncthreads();
    }
    if (idx < NN) g_ps[idx] = sm[t];
    if (t == 511) g_blk[blockIdx.x] = sm[511];
}
__global__ void k_scan2(int nblk) {
    if (threadIdx.x == 0) {
        int run = 0;
        for (int i = 0; i < nblk; i++) { g_blkoff[i] = run; run += g_blk[i]; }
    }
}
__global__ __launch_bounds__(512) void k_scan3() {
    int idx = blockIdx.x*512 + threadIdx.x;
    if (idx < NN) {
        g_rowptr[idx+1] = g_ps[idx] + g_blkoff[blockIdx.x];
        g_cur[idx] = 0;
        if (idx == 0) g_rowptr[0] = 0;
    }
}
__global__ void k_fill(const int* __restrict__ ei, const float* __restrict__ ew,
                       const float* __restrict__ ea) {
    int e = blockIdx.x*256 + threadIdx.x;
    int s = ei[e], d = ei[EE+e];
    int pos = g_rowptr[d] + atomicAdd(&g_cur[d], 1);
    g_cpk[pos] = make_int2(s, __float_as_int(g_dinv[s] * ew[e] * g_dinv[d]));
    g_cdst[pos] = d;
    g_cea[pos]  = ea[e];
}

// -------- GCN gather + silu + residual + LN (warp per node, half-warp per edge) -----
__global__ __launch_bounds__(256) void k_gcn_ln(
    const float* __restrict__ gb, const float* __restrict__ lg, const float* __restrict__ lb)
{
    int row = blockIdx.x*8 + (threadIdx.x >> 5);
    if (row >= NN) return;
    int lane = threadIdx.x & 31;
    int q = lane & 15, half = lane >> 4;
    int start = g_rowptr[row], end = g_rowptr[row+1];
    float4 acc = make_float4(0.f, 0.f, 0.f, 0.f);
    if (half == 0) {
        float dv = g_dinv[row];
        float ss = dv * dv;
        float4 hv = *(const float4*)&g_h[row*64 + q*4];
        acc.x = hv.x*ss; acc.y = hv.y*ss; acc.z = hv.z*ss; acc.w = hv.w*ss;
    }
    for (int j = start + half; j < end; j += 2) {
        int2 pk = __ldg(&g_cpk[j]);
        float w = __int_as_float(pk.y);
        float4 v = *(const float4*)&g_h[pk.x*64 + q*4];
        acc.x += w*v.x; acc.y += w*v.y; acc.z += w*v.z; acc.w += w*v.w;
    }
    acc.x += __shfl_xor_sync(FULL, acc.x, 16);
    acc.y += __shfl_xor_sync(FULL, acc.y, 16);
    acc.z += __shfl_xor_sync(FULL, acc.z, 16);
    acc.w += __shfl_xor_sync(FULL, acc.w, 16);
    // both halves now hold the full sums; compute LN redundantly, half 0 stores
    float4 gb4 = *(const float4*)&gb[q*4];
    float4 rs4 = *(const float4*)&g_res[row*64 + q*4];
    float4 v;
    v.x = siluf(acc.x + gb4.x) + rs4.x;
    v.y = siluf(acc.y + gb4.y) + rs4.y;
    v.z = siluf(acc.z + gb4.z) + rs4.z;
    v.w = siluf(acc.w + gb4.w) + rs4.w;
    float sum = v.x + v.y + v.z + v.w;
    #pragma unroll
    for (int o = 8; o; o >>= 1) sum += __shfl_xor_sync(FULL, sum, o);
    float mu = sum * (1.f/64.f);
    float4 d;
    d.x = v.x - mu; d.y = v.y - mu; d.z = v.z - mu; d.w = v.w - mu;
    float vs = d.x*d.x + d.y*d.y + d.z*d.z + d.w*d.w;
    #pragma unroll
    for (int o = 8; o; o >>= 1) vs += __shfl_xor_sync(FULL, vs, o);
    float inv = rsqrtf(vs * (1.f/64.f) + 1e-5f);
    if (half == 0) {
        float4 lg4 = *(const float4*)&lg[q*4];
        float4 lb4 = *(const float4*)&lb[q*4];
        float4 o4;
        o4.x = d.x*inv*lg4.x + lb4.x;
        o4.y = d.y*inv*lg4.y + lb4.y;
        o4.z = d.z*inv*lg4.z + lb4.z;
        o4.w = d.w*inv*lg4.w + lb4.w;
        *(float4*)&g_xln[row*64 + q*4] = o4;
    }
}

// ---------------- GAT ----------------
// ce[h] = sum_c We[h*16+c]*a_e[h*16+c]; ce[4] = mean(edge_attr)
__global__ void k_ce(const float* __restrict__ eww, const float* __restrict__ ae) {
    int lane = threadIdx.x;
    float p0 = eww[lane]*ae[lane];
    float p1 = eww[lane+32]*ae[lane+32];
    #pragma unroll
    for (int o = 8; o; o >>= 1) {
        p0 += __shfl_xor_sync(FULL, p0, o);
        p1 += __shfl_xor_sync(FULL, p1, o);
    }
    if ((lane & 15) == 0) {
        g_ce[lane >> 4]       = p0;
        g_ce[2 + (lane >> 4)] = p1;
    }
    if (lane == 0) g_ce[4] = g_easum * (1.f / EE);
}
// CSR-ordered edge-parallel: exp(alpha) written linearly
__global__ void k_gatA() {
    int e = blockIdx.x*256 + threadIdx.x;   // CSR slot
    int s = g_cpk[e].x, d = g_cdst[e];
    float eav = g_cea[e];
    float4 av = *(const float4*)&g_as[s*4];
    float4 dv = *(const float4*)&g_ad[d*4];
    float4 ce = *(const float4*)&g_ce[0];
    float4 p;
    p.x = __expf(fminf(lrelu(av.x + dv.x + eav*ce.x), 70.f));
    p.y = __expf(fminf(lrelu(av.y + dv.y + eav*ce.y), 70.f));
    p.z = __expf(fminf(lrelu(av.z + dv.z + eav*ce.z), 70.f));
    p.w = __expf(fminf(lrelu(av.w + dv.w + eav*ce.w), 70.f));
    *(float4*)&g_ep[e*4] = p;
}
// warp-per-node, half-warp per edge: gather + inline softmax denom + silu + skip
__global__ __launch_bounds__(256) void k_gat_gather(
    const float* __restrict__ bg, float* __restrict__ xout)
{
    int row = blockIdx.x*8 + (threadIdx.x >> 5);
    if (row >= NN) return;
    int lane = threadIdx.x & 31;
    int q = lane & 15, half = lane >> 4;
    int h = q >> 2;                          // head of this lane's 4 columns
    int start = g_rowptr[row], end = g_rowptr[row+1];
    // self-loop exp(alpha)
    float4 av = *(const float4*)&g_as[row*4];
    float4 dv = *(const float4*)&g_ad[row*4];
    float4 ce = *(const float4*)&g_ce[0];
    float cm = g_ce[4];
    float4 ps;
    ps.x = __expf(fminf(lrelu(av.x + dv.x + cm*ce.x), 70.f));
    ps.y = __expf(fminf(lrelu(av.y + dv.y + cm*ce.y), 70.f));
    ps.z = __expf(fminf(lrelu(av.z + dv.z + cm*ce.z), 70.f));
    ps.w = __expf(fminf(lrelu(av.w + dv.w + cm*ce.w), 70.f));
    float p_self = (q < 8) ? ((q < 4) ? ps.x : ps.y) : ((q < 12) ? ps.z : ps.w);
    float4 acc = make_float4(0.f, 0.f, 0.f, 0.f);
    float sa = 0.f;
    if (half == 0) {
        float4 xv = *(const float4*)&g_xg[row*64 + q*4];
        acc.x = xv.x*p_self; acc.y = xv.y*p_self; acc.z = xv.z*p_self; acc.w = xv.w*p_self;
        sa = p_self;
    }
    for (int j = start + half; j < end; j += 2) {
        int s = __ldg(&g_cpk[j]).x;
        float p = __ldg(&g_ep[j*4 + h]);
        float4 v = *(const float4*)&g_xg[s*64 + q*4];
        acc.x += p*v.x; acc.y += p*v.y; acc.z += p*v.z; acc.w += p*v.w;
        sa += p;
    }
    acc.x += __shfl_xor_sync(FULL, acc.x, 16);
    acc.y += __shfl_xor_sync(FULL, acc.y, 16);
    acc.z += __shfl_xor_sync(FULL, acc.z, 16);
    acc.w += __shfl_xor_sync(FULL, acc.w, 16);
    sa    += __shfl_xor_sync(FULL, sa, 16);
    if (half == 0) {
        float ia = 1.f / (sa + 1e-16f);
        float4 bg4 = *(const float4*)&bg[q*4];
        float4 xl4 = *(const float4*)&g_xln[row*64 + q*4];
        float* o = xout ? xout : g_xcur;
        float4 o4;
        o4.x = siluf(acc.x*ia + bg4.x) + xl4.x;
        o4.y = siluf(acc.y*ia + bg4.y) + xl4.y;
        o4.z = siluf(acc.z*ia + bg4.z) + xl4.z;
        o4.w = siluf(acc.w*ia + bg4.w) + xl4.w;
        *(float4*)&o[row*64 + q*4] = o4;
    }
}

// ---------------- launch ----------------
extern "C" void kernel_launch(void* const* d_in, const int* in_sizes, int n_in,
                              void* d_out, int out_size) {
    (void)in_sizes; (void)n_in; (void)out_size;
    const float* x  = (const float*)d_in[0];
    const int*   ei = (const int*)  d_in[1];
    const float* ew = (const float*)d_in[2];
    const float* ea = (const float*)d_in[3];

    // graph-structure setup (layer-independent)
    k_init<<<196,256>>>();
    k_deg_edge<<<3125,256>>>(ei, ew, ea);
    k_scan1<<<98,512>>>();
    k_scan2<<<1,32>>>(98);
    k_scan3<<<98,512>>>();
    k_fill<<<3125,256>>>(ei, ew, ea);

    for (int L = 0; L < 2; L++) {
        const float* gw  = (const float*)d_in[4+12*L+0];
        const float* gb  = (const float*)d_in[4+12*L+1];
        const float* rw  = (const float*)d_in[4+12*L+2];
        const float* rb  = (const float*)d_in[4+12*L+3];
        const float* lg  = (const float*)d_in[4+12*L+4];
        const float* lb  = (const float*)d_in[4+12*L+5];
        const float* Wg  = (const float*)d_in[4+12*L+6];
        const float* bg  = (const float*)d_in[4+12*L+7];
        const float* asv = (const float*)d_in[4+12*L+8];
        const float* adv = (const float*)d_in[4+12*L+9];
        const float* aev = (const float*)d_in[4+12*L+10];
        const float* eww = (const float*)d_in[4+12*L+11];

        const float* xin  = (L == 0) ? x : nullptr;             // null -> g_xcur
        float*       xout = (L == 1) ? (float*)d_out : nullptr; // null -> g_xcur

        k_gemm_dual<<<1563,256>>>(xin, gw, rw, rb);
        k_gcn_ln<<<6250,256>>>(gb, lg, lb);
        k_gemm_gat<<<782,256>>>(Wg, asv, adv);
        k_ce<<<1,32>>>(eww, aev);
        k_gatA<<<3125,256>>>();
        k_gat_gather<<<6250,256>>>(bg, xout);
    }
}

// round 13
// speedup vs baseline: 1.1754x; 1.0801x over previous
#include <cuda_runtime.h>

#define NN 50000
#define EE 800000
#define FULL 0xffffffffu

// ---------------- scratch (static device globals; no allocs) ----------------
static __device__ float g_h[NN*64];      // GCN-transformed features
static __device__ float g_res[NN*64];    // residual branch
static __device__ float g_xln[NN*64];    // post-GCN layernorm output
static __device__ float g_xg[NN*64];     // GAT-transformed features
static __device__ float g_xcur[NN*64];   // layer-0 output
static __device__ float g_deg[NN];
static __device__ float g_dinv[NN];
static __device__ int   g_cnt[NN];       // in-degree counts (edges only)
static __device__ int   g_ps[NN];        // inclusive scan scratch
static __device__ int   g_blk[128];      // block sums
static __device__ int   g_blkoff[128];
static __device__ int   g_rowptr[NN+1];
static __device__ int   g_cur[NN];
static __device__ int2  g_cpk[EE];       // CSR slot -> (src, gcn-weight bits)
static __device__ int   g_cdst[EE];      // CSR dst node per slot
static __device__ float g_cea[EE];       // CSR edge_attr per slot
static __device__ float g_as[NN*4];
static __device__ float g_ad[NN*4];
static __device__ float g_ep[EE*4];      // exp(alpha) per CSR slot, 4 heads
static __device__ float g_ce[8];         // [0..3]=ce per head, [4]=mean(edge_attr)
static __device__ float g_easum;

// ---------------- helpers ----------------
__device__ __forceinline__ float siluf(float v) { return v * (1.f / (1.f + __expf(-v))); }
__device__ __forceinline__ float lrelu(float v) { return v >= 0.f ? v : 0.2f * v; }

// ---------------- GEMMs ----------------
// g_h = x@W0, g_res = x@W1 + b1. 32-row tile, 256 threads.
__global__ __launch_bounds__(256) void k_gemm_dual(
    const float* __restrict__ xin, const float* __restrict__ W0,
    const float* __restrict__ W1, const float* __restrict__ b1)
{
    const float* x = xin ? xin : g_xcur;
    __shared__ float xs[32*68];
    __shared__ float ws[2][64*68];
    int t = threadIdx.x;
    int row0 = blockIdx.x * 32;
    for (int i = t; i < 4096; i += 256) {
        int k = i >> 6, c = i & 63;
        ws[0][k*68+c] = W0[i];
        ws[1][k*68+c] = W1[i];
    }
    for (int i = t; i < 2048; i += 256) {
        int r = i >> 6, c = i & 63;
        xs[r*68+c] = (row0 + r < NN) ? x[(row0+r)*64 + c] : 0.f;
    }
    __syncthreads();
    int rg = t >> 4, g = t & 15, m = g >> 3, cb = (g & 7) * 8;
    const float* wp = ws[m];
    int r0 = rg*2, r1 = r0 + 1;
    float a0[8], a1[8];
    #pragma unroll
    for (int j = 0; j < 8; j++) { a0[j] = 0.f; a1[j] = 0.f; }
    #pragma unroll 16
    for (int k = 0; k < 64; k++) {
        float xv0 = xs[r0*68+k], xv1 = xs[r1*68+k];
        float w[8];
        *(float4*)&w[0] = *(const float4*)&wp[k*68+cb];
        *(float4*)&w[4] = *(const float4*)&wp[k*68+cb+4];
        #pragma unroll
        for (int j = 0; j < 8; j++) { a0[j] += xv0 * w[j]; a1[j] += xv1 * w[j]; }
    }
    float* y = m ? g_res : g_h;
    if (m) {
        #pragma unroll
        for (int j = 0; j < 8; j++) { float b = b1[cb+j]; a0[j] += b; a1[j] += b; }
    }
    if (row0 + r0 < NN) {
        *(float4*)&y[(row0+r0)*64+cb]   = *(float4*)&a0[0];
        *(float4*)&y[(row0+r0)*64+cb+4] = *(float4*)&a0[4];
    }
    if (row0 + r1 < NN) {
        *(float4*)&y[(row0+r1)*64+cb]   = *(float4*)&a1[0];
        *(float4*)&y[(row0+r1)*64+cb+4] = *(float4*)&a1[4];
    }
}

// g_xg = g_xln @ W ; fused attention dots g_as/g_ad. 64-row tile, 256 threads.
__global__ __launch_bounds__(256) void k_gemm_gat(
    const float* __restrict__ W,
    const float* __restrict__ asrc, const float* __restrict__ adst)
{
    __shared__ float xs[64*68];
    __shared__ float ws[64*68];
    int t = threadIdx.x;
    int row0 = blockIdx.x * 64;
    for (int i = t; i < 4096; i += 256) {
        int k = i >> 6, c = i & 63;
        ws[k*68+c] = W[i];
    }
    for (int i = t; i < 4096; i += 256) {
        int r = i >> 6, c = i & 63;
        xs[r*68+c] = (row0 + r < NN) ? g_xln[(row0+r)*64 + c] : 0.f;
    }
    __syncthreads();
    int rg = t >> 3, cb = (t & 7) * 8;
    int r0 = rg*2, r1 = r0 + 1;
    float a0[8], a1[8];
    #pragma unroll
    for (int j = 0; j < 8; j++) { a0[j] = 0.f; a1[j] = 0.f; }
    #pragma unroll 16
    for (int k = 0; k < 64; k++) {
        float xv0 = xs[r0*68+k], xv1 = xs[r1*68+k];
        float w[8];
        *(float4*)&w[0] = *(const float4*)&ws[k*68+cb];
        *(float4*)&w[4] = *(const float4*)&ws[k*68+cb+4];
        #pragma unroll
        for (int j = 0; j < 8; j++) { a0[j] += xv0 * w[j]; a1[j] += xv1 * w[j]; }
    }
    if (row0 + r0 < NN) {
        *(float4*)&g_xg[(row0+r0)*64+cb]   = *(float4*)&a0[0];
        *(float4*)&g_xg[(row0+r0)*64+cb+4] = *(float4*)&a0[4];
    }
    if (row0 + r1 < NN) {
        *(float4*)&g_xg[(row0+r1)*64+cb]   = *(float4*)&a1[0];
        *(float4*)&g_xg[(row0+r1)*64+cb+4] = *(float4*)&a1[4];
    }
    // fused attention dots: thread pair (t, t^1) covers one head (16 cols)
    float s0 = 0.f, s1 = 0.f, d0 = 0.f, d1 = 0.f;
    #pragma unroll
    for (int j = 0; j < 8; j++) {
        float av = asrc[cb+j], dv = adst[cb+j];
        s0 += a0[j]*av; d0 += a0[j]*dv;
        s1 += a1[j]*av; d1 += a1[j]*dv;
    }
    s0 += __shfl_xor_sync(FULL, s0, 1);
    s1 += __shfl_xor_sync(FULL, s1, 1);
    d0 += __shfl_xor_sync(FULL, d0, 1);
    d1 += __shfl_xor_sync(FULL, d1, 1);
    if ((t & 1) == 0) {
        int hh = cb >> 4;
        if (row0 + r0 < NN) { g_as[(row0+r0)*4+hh] = s0; g_ad[(row0+r0)*4+hh] = d0; }
        if (row0 + r1 < NN) { g_as[(row0+r1)*4+hh] = s1; g_ad[(row0+r1)*4+hh] = d1; }
    }
}

// ---------------- graph setup (once per call) ----------------
__global__ void k_init() {
    int i = blockIdx.x*256 + threadIdx.x;
    if (i < NN) { g_deg[i] = 1.f; g_cnt[i] = 0; }
    if (i == 0) g_easum = 0.f;
}
__global__ void k_easum(const float* __restrict__ ea) {
    __shared__ float ss[8];
    float sum = 0.f;
    for (int i = blockIdx.x*blockDim.x + threadIdx.x; i < EE; i += gridDim.x*blockDim.x)
        sum += ea[i];
    #pragma unroll
    for (int o = 16; o; o >>= 1) sum += __shfl_xor_sync(FULL, sum, o);
    if ((threadIdx.x & 31) == 0) ss[threadIdx.x >> 5] = sum;
    __syncthreads();
    if (threadIdx.x < 8) {
        float v = ss[threadIdx.x];
        #pragma unroll
        for (int o = 4; o; o >>= 1) v += __shfl_xor_sync(0xffu, v, o);
        if (threadIdx.x == 0) atomicAdd(&g_easum, v);
    }
}
__global__ void k_deg_edge(const int* __restrict__ ei, const float* __restrict__ ew) {
    int e = blockIdx.x*256 + threadIdx.x;
    int d = ei[EE+e];
    atomicAdd(&g_deg[d], ew[e]);
    atomicAdd(&g_cnt[d], 1);
}
__global__ __launch_bounds__(512) void k_scan1() {
    __shared__ int sm[512];
    int t = threadIdx.x;
    int idx = blockIdx.x*512 + t;
    if (idx < NN) g_dinv[idx] = rsqrtf(g_deg[idx]);
    int c = (idx < NN) ? g_cnt[idx] : 0;
    sm[t] = c; __syncthreads();
    #pragma unroll
    for (int off = 1; off < 512; off <<= 1) {
        int v = (t >= off) ? sm[t-off] : 0;
        __syncthreads();
        sm[t] += v;
        __syncthreads();
    }
    if (idx < NN) g_ps[idx] = sm[t];
    if (t == 511) g_blk[blockIdx.x] = sm[511];
}
// parallel exclusive scan of 98 block sums: one warp, 4 elems/lane
__global__ void k_scan2(int nblk) {
    int lane = threadIdx.x;              // 32 threads
    int v[4];
    int base = lane * 4;
    #pragma unroll
    for (int i = 0; i < 4; i++) {
        int idx = base + i;
        v[i] = (idx < nblk) ? g_blk[idx] : 0;
    }
    int local = v[0] + v[1] + v[2] + v[3];
    // inclusive warp scan of per-lane totals
    int scan = local;
    #pragma unroll
    for (int o = 1; o < 32; o <<= 1) {
        int n = __shfl_up_sync(FULL, scan, o);
        if (lane >= o) scan += n;
    }
    int excl = scan - local;             // exclusive prefix of this lane's chunk
    int run = excl;
    #pragma unroll
    for (int i = 0; i < 4; i++) {
        int idx = base + i;
        if (idx < nblk) g_blkoff[idx] = run;
        run += v[i];
    }
}
__global__ __launch_bounds__(512) void k_scan3() {
    int idx = blockIdx.x*512 + threadIdx.x;
    if (idx < NN) {
        g_rowptr[idx+1] = g_ps[idx] + g_blkoff[blockIdx.x];
        g_cur[idx] = 0;
        if (idx == 0) g_rowptr[0] = 0;
    }
}
__global__ void k_fill(const int* __restrict__ ei, const float* __restrict__ ew,
                       const float* __restrict__ ea) {
    int e = blockIdx.x*256 + threadIdx.x;
    int s = ei[e], d = ei[EE+e];
    int pos = g_rowptr[d] + atomicAdd(&g_cur[d], 1);
    g_cpk[pos] = make_int2(s, __float_as_int(g_dinv[s] * ew[e] * g_dinv[d]));
    g_cdst[pos] = d;
    g_cea[pos]  = ea[e];
}

// -------- GCN gather + silu + residual + LN (warp per node, half-warp per edge) -----
__global__ __launch_bounds__(256) void k_gcn_ln(
    const float* __restrict__ gb, const float* __restrict__ lg, const float* __restrict__ lb)
{
    int row = blockIdx.x*8 + (threadIdx.x >> 5);
    if (row >= NN) return;
    int lane = threadIdx.x & 31;
    int q = lane & 15, half = lane >> 4;
    int start = g_rowptr[row], end = g_rowptr[row+1];
    float4 acc = make_float4(0.f, 0.f, 0.f, 0.f);
    if (half == 0) {
        float dv = g_dinv[row];
        float ss = dv * dv;
        float4 hv = *(const float4*)&g_h[row*64 + q*4];
        acc.x = hv.x*ss; acc.y = hv.y*ss; acc.z = hv.z*ss; acc.w = hv.w*ss;
    }
    for (int j = start + half; j < end; j += 2) {
        int2 pk = __ldg(&g_cpk[j]);
        float w = __int_as_float(pk.y);
        float4 v = *(const float4*)&g_h[pk.x*64 + q*4];
        acc.x += w*v.x; acc.y += w*v.y; acc.z += w*v.z; acc.w += w*v.w;
    }
    acc.x += __shfl_xor_sync(FULL, acc.x, 16);
    acc.y += __shfl_xor_sync(FULL, acc.y, 16);
    acc.z += __shfl_xor_sync(FULL, acc.z, 16);
    acc.w += __shfl_xor_sync(FULL, acc.w, 16);
    // both halves now hold the full sums; compute LN redundantly, half 0 stores
    float4 gb4 = *(const float4*)&gb[q*4];
    float4 rs4 = *(const float4*)&g_res[row*64 + q*4];
    float4 v;
    v.x = siluf(acc.x + gb4.x) + rs4.x;
    v.y = siluf(acc.y + gb4.y) + rs4.y;
    v.z = siluf(acc.z + gb4.z) + rs4.z;
    v.w = siluf(acc.w + gb4.w) + rs4.w;
    float sum = v.x + v.y + v.z + v.w;
    #pragma unroll
    for (int o = 8; o; o >>= 1) sum += __shfl_xor_sync(FULL, sum, o);
    float mu = sum * (1.f/64.f);
    float4 d;
    d.x = v.x - mu; d.y = v.y - mu; d.z = v.z - mu; d.w = v.w - mu;
    float vs = d.x*d.x + d.y*d.y + d.z*d.z + d.w*d.w;
    #pragma unroll
    for (int o = 8; o; o >>= 1) vs += __shfl_xor_sync(FULL, vs, o);
    float inv = rsqrtf(vs * (1.f/64.f) + 1e-5f);
    if (half == 0) {
        float4 lg4 = *(const float4*)&lg[q*4];
        float4 lb4 = *(const float4*)&lb[q*4];
        float4 o4;
        o4.x = d.x*inv*lg4.x + lb4.x;
        o4.y = d.y*inv*lg4.y + lb4.y;
        o4.z = d.z*inv*lg4.z + lb4.z;
        o4.w = d.w*inv*lg4.w + lb4.w;
        *(float4*)&g_xln[row*64 + q*4] = o4;
    }
}

// ---------------- GAT ----------------
// ce[h] = sum_c We[h*16+c]*a_e[h*16+c]; ce[4] = mean(edge_attr)
__global__ void k_ce(const float* __restrict__ eww, const float* __restrict__ ae) {
    int lane = threadIdx.x;
    float p0 = eww[lane]*ae[lane];
    float p1 = eww[lane+32]*ae[lane+32];
    #pragma unroll
    for (int o = 8; o; o >>= 1) {
        p0 += __shfl_xor_sync(FULL, p0, o);
        p1 += __shfl_xor_sync(FULL, p1, o);
    }
    if ((lane & 15) == 0) {
        g_ce[lane >> 4]       = p0;
        g_ce[2 + (lane >> 4)] = p1;
    }
    if (lane == 0) g_ce[4] = g_easum * (1.f / EE);
}
// CSR-ordered edge-parallel: exp(alpha) written linearly
__global__ void k_gatA() {
    int e = blockIdx.x*256 + threadIdx.x;   // CSR slot
    int s = g_cpk[e].x, d = g_cdst[e];
    float eav = g_cea[e];
    float4 av = *(const float4*)&g_as[s*4];
    float4 dv = *(const float4*)&g_ad[d*4];
    float4 ce = *(const float4*)&g_ce[0];
    float4 p;
    p.x = __expf(fminf(lrelu(av.x + dv.x + eav*ce.x), 70.f));
    p.y = __expf(fminf(lrelu(av.y + dv.y + eav*ce.y), 70.f));
    p.z = __expf(fminf(lrelu(av.z + dv.z + eav*ce.z), 70.f));
    p.w = __expf(fminf(lrelu(av.w + dv.w + eav*ce.w), 70.f));
    *(float4*)&g_ep[e*4] = p;
}
// warp-per-node, half-warp per edge: gather + inline softmax denom + silu + skip
__global__ __launch_bounds__(256) void k_gat_gather(
    const float* __restrict__ bg, float* __restrict__ xout)
{
    int row = blockIdx.x*8 + (threadIdx.x >> 5);
    if (row >= NN) return;
    int lane = threadIdx.x & 31;
    int q = lane & 15, half = lane >> 4;
    int h = q >> 2;                          // head of this lane's 4 columns
    int start = g_rowptr[row], end = g_rowptr[row+1];
    // self-loop exp(alpha)
    float4 av = *(const float4*)&g_as[row*4];
    float4 dv = *(const float4*)&g_ad[row*4];
    float4 ce = *(const float4*)&g_ce[0];
    float cm = g_ce[4];
    float4 ps;
    ps.x = __expf(fminf(lrelu(av.x + dv.x + cm*ce.x), 70.f));
    ps.y = __expf(fminf(lrelu(av.y + dv.y + cm*ce.y), 70.f));
    ps.z = __expf(fminf(lrelu(av.z + dv.z + cm*ce.z), 70.f));
    ps.w = __expf(fminf(lrelu(av.w + dv.w + cm*ce.w), 70.f));
    float p_self = (q < 8) ? ((q < 4) ? ps.x : ps.y) : ((q < 12) ? ps.z : ps.w);
    float4 acc = make_float4(0.f, 0.f, 0.f, 0.f);
    float sa = 0.f;
    if (half == 0) {
        float4 xv = *(const float4*)&g_xg[row*64 + q*4];
        acc.x = xv.x*p_self; acc.y = xv.y*p_self; acc.z = xv.z*p_self; acc.w = xv.w*p_self;
        sa = p_self;
    }
    for (int j = start + half; j < end; j += 2) {
        int s = __ldg(&g_cpk[j]).x;
        float p = __ldg(&g_ep[j*4 + h]);
        float4 v = *(const float4*)&g_xg[s*64 + q*4];
        acc.x += p*v.x; acc.y += p*v.y; acc.z += p*v.z; acc.w += p*v.w;
        sa += p;
    }
    acc.x += __shfl_xor_sync(FULL, acc.x, 16);
    acc.y += __shfl_xor_sync(FULL, acc.y, 16);
    acc.z += __shfl_xor_sync(FULL, acc.z, 16);
    acc.w += __shfl_xor_sync(FULL, acc.w, 16);
    sa    += __shfl_xor_sync(FULL, sa, 16);
    if (half == 0) {
        float ia = 1.f / (sa + 1e-16f);
        float4 bg4 = *(const float4*)&bg[q*4];
        float4 xl4 = *(const float4*)&g_xln[row*64 + q*4];
        float* o = xout ? xout : g_xcur;
        float4 o4;
        o4.x = siluf(acc.x*ia + bg4.x) + xl4.x;
        o4.y = siluf(acc.y*ia + bg4.y) + xl4.y;
        o4.z = siluf(acc.z*ia + bg4.z) + xl4.z;
        o4.w = siluf(acc.w*ia + bg4.w) + xl4.w;
        *(float4*)&o[row*64 + q*4] = o4;
    }
}

// ---------------- launch ----------------
extern "C" void kernel_launch(void* const* d_in, const int* in_sizes, int n_in,
                              void* d_out, int out_size) {
    (void)in_sizes; (void)n_in; (void)out_size;
    const float* x  = (const float*)d_in[0];
    const int*   ei = (const int*)  d_in[1];
    const float* ew = (const float*)d_in[2];
    const float* ea = (const float*)d_in[3];

    // graph-structure setup (layer-independent)
    k_init<<<196,256>>>();
    k_easum<<<1024,256>>>(ea);
    k_deg_edge<<<3125,256>>>(ei, ew);
    k_scan1<<<98,512>>>();
    k_scan2<<<1,32>>>(98);
    k_scan3<<<98,512>>>();
    k_fill<<<3125,256>>>(ei, ew, ea);

    for (int L = 0; L < 2; L++) {
        const float* gw  = (const float*)d_in[4+12*L+0];
        const float* gb  = (const float*)d_in[4+12*L+1];
        const float* rw  = (const float*)d_in[4+12*L+2];
        const float* rb  = (const float*)d_in[4+12*L+3];
        const float* lg  = (const float*)d_in[4+12*L+4];
        const float* lb  = (const float*)d_in[4+12*L+5];
        const float* Wg  = (const float*)d_in[4+12*L+6];
        const float* bg  = (const float*)d_in[4+12*L+7];
        const float* asv = (const float*)d_in[4+12*L+8];
        const float* adv = (const float*)d_in[4+12*L+9];
        const float* aev = (const float*)d_in[4+12*L+10];
        const float* eww = (const float*)d_in[4+12*L+11];

        const float* xin  = (L == 0) ? x : nullptr;             // null -> g_xcur
        float*       xout = (L == 1) ? (float*)d_out : nullptr; // null -> g_xcur

        k_gemm_dual<<<1563,256>>>(xin, gw, rw, rb);
        k_gcn_ln<<<6250,256>>>(gb, lg, lb);
        k_gemm_gat<<<782,256>>>(Wg, asv, adv);
        k_ce<<<1,32>>>(eww, aev);
        k_gatA<<<3125,256>>>();
        k_gat_gather<<<6250,256>>>(bg, xout);
    }
}

// round 14
// speedup vs baseline: 1.1815x; 1.0052x over previous
#include <cuda_runtime.h>

#define NN 50000
#define EE 800000
#define FULL 0xffffffffu

// ---------------- scratch (static device globals; no allocs) ----------------
static __device__ float  g_h[NN*64];      // GCN-transformed features
static __device__ float  g_res[NN*64];    // residual branch
static __device__ float  g_xln[NN*64];    // post-GCN layernorm output
static __device__ float  g_xg[NN*64];     // GAT-transformed features
static __device__ float  g_xcur[NN*64];   // layer-0 output
static __device__ float2 g_dc[NN];        // (deg, cnt) packed
static __device__ float  g_dinv[NN];
static __device__ int    g_ps[NN];        // inclusive scan scratch
static __device__ int    g_blk[128];      // block sums
static __device__ int    g_blkoff[128];
static __device__ int    g_rowptr[NN+1];
static __device__ int    g_cur[NN];
static __device__ int2   g_cpk[EE];       // CSR slot -> (src, gcn-weight bits)
static __device__ int    g_cdst[EE];      // CSR dst node per slot
static __device__ float  g_cea[EE];       // CSR edge_attr per slot
static __device__ float  g_as[NN*4];
static __device__ float  g_ad[NN*4];
static __device__ float  g_ep[EE*4];      // exp(alpha) per CSR slot, 4 heads
static __device__ float  g_epart[1024];   // easum partials
static __device__ float  g_easum;

// ---------------- helpers ----------------
__device__ __forceinline__ float siluf(float v) { return v * (1.f / (1.f + __expf(-v))); }
__device__ __forceinline__ float lrelu(float v) { return v >= 0.f ? v : 0.2f * v; }
__device__ __forceinline__ void red_add_v2(float2* a, float x, float y) {
    asm volatile("red.global.add.v2.f32 [%0], {%1,%2};"
                 :: "l"(a), "f"(x), "f"(y) : "memory");
}

// ---------------- GEMMs ----------------
// g_h = x@W0, g_res = x@W1 + b1. 32-row tile, 256 threads.
__global__ __launch_bounds__(256) void k_gemm_dual(
    const float* __restrict__ xin, const float* __restrict__ W0,
    const float* __restrict__ W1, const float* __restrict__ b1)
{
    const float* x = xin ? xin : g_xcur;
    __shared__ float xs[32*68];
    __shared__ float ws[2][64*68];
    int t = threadIdx.x;
    int row0 = blockIdx.x * 32;
    for (int i = t; i < 4096; i += 256) {
        int k = i >> 6, c = i & 63;
        ws[0][k*68+c] = W0[i];
        ws[1][k*68+c] = W1[i];
    }
    for (int i = t; i < 2048; i += 256) {
        int r = i >> 6, c = i & 63;
        xs[r*68+c] = (row0 + r < NN) ? x[(row0+r)*64 + c] : 0.f;
    }
    __syncthreads();
    int rg = t >> 4, g = t & 15, m = g >> 3, cb = (g & 7) * 8;
    const float* wp = ws[m];
    int r0 = rg*2, r1 = r0 + 1;
    float a0[8], a1[8];
    #pragma unroll
    for (int j = 0; j < 8; j++) { a0[j] = 0.f; a1[j] = 0.f; }
    #pragma unroll 16
    for (int k = 0; k < 64; k++) {
        float xv0 = xs[r0*68+k], xv1 = xs[r1*68+k];
        float w[8];
        *(float4*)&w[0] = *(const float4*)&wp[k*68+cb];
        *(float4*)&w[4] = *(const float4*)&wp[k*68+cb+4];
        #pragma unroll
        for (int j = 0; j < 8; j++) { a0[j] += xv0 * w[j]; a1[j] += xv1 * w[j]; }
    }
    float* y = m ? g_res : g_h;
    if (m) {
        #pragma unroll
        for (int j = 0; j < 8; j++) { float b = b1[cb+j]; a0[j] += b; a1[j] += b; }
    }
    if (row0 + r0 < NN) {
        *(float4*)&y[(row0+r0)*64+cb]   = *(float4*)&a0[0];
        *(float4*)&y[(row0+r0)*64+cb+4] = *(float4*)&a0[4];
    }
    if (row0 + r1 < NN) {
        *(float4*)&y[(row0+r1)*64+cb]   = *(float4*)&a1[0];
        *(float4*)&y[(row0+r1)*64+cb+4] = *(float4*)&a1[4];
    }
}

// g_xg = g_xln @ W ; fused attention dots g_as/g_ad. 64-row tile, 256 threads.
__global__ __launch_bounds__(256) void k_gemm_gat(
    const float* __restrict__ W,
    const float* __restrict__ asrc, const float* __restrict__ adst)
{
    __shared__ float xs[64*68];
    __shared__ float ws[64*68];
    int t = threadIdx.x;
    int row0 = blockIdx.x * 64;
    for (int i = t; i < 4096; i += 256) {
        int k = i >> 6, c = i & 63;
        ws[k*68+c] = W[i];
    }
    for (int i = t; i < 4096; i += 256) {
        int r = i >> 6, c = i & 63;
        xs[r*68+c] = (row0 + r < NN) ? g_xln[(row0+r)*64 + c] : 0.f;
    }
    __syncthreads();
    int rg = t >> 3, cb = (t & 7) * 8;
    int r0 = rg*2, r1 = r0 + 1;
    float a0[8], a1[8];
    #pragma unroll
    for (int j = 0; j < 8; j++) { a0[j] = 0.f; a1[j] = 0.f; }
    #pragma unroll 16
    for (int k = 0; k < 64; k++) {
        float xv0 = xs[r0*68+k], xv1 = xs[r1*68+k];
        float w[8];
        *(float4*)&w[0] = *(const float4*)&ws[k*68+cb];
        *(float4*)&w[4] = *(const float4*)&ws[k*68+cb+4];
        #pragma unroll
        for (int j = 0; j < 8; j++) { a0[j] += xv0 * w[j]; a1[j] += xv1 * w[j]; }
    }
    if (row0 + r0 < NN) {
        *(float4*)&g_xg[(row0+r0)*64+cb]   = *(float4*)&a0[0];
        *(float4*)&g_xg[(row0+r0)*64+cb+4] = *(float4*)&a0[4];
    }
    if (row0 + r1 < NN) {
        *(float4*)&g_xg[(row0+r1)*64+cb]   = *(float4*)&a1[0];
        *(float4*)&g_xg[(row0+r1)*64+cb+4] = *(float4*)&a1[4];
    }
    // fused attention dots: thread pair (t, t^1) covers one head (16 cols)
    float s0 = 0.f, s1 = 0.f, d0 = 0.f, d1 = 0.f;
    #pragma unroll
    for (int j = 0; j < 8; j++) {
        float av = asrc[cb+j], dv = adst[cb+j];
        s0 += a0[j]*av; d0 += a0[j]*dv;
        s1 += a1[j]*av; d1 += a1[j]*dv;
    }
    s0 += __shfl_xor_sync(FULL, s0, 1);
    s1 += __shfl_xor_sync(FULL, s1, 1);
    d0 += __shfl_xor_sync(FULL, d0, 1);
    d1 += __shfl_xor_sync(FULL, d1, 1);
    if ((t & 1) == 0) {
        int hh = cb >> 4;
        if (row0 + r0 < NN) { g_as[(row0+r0)*4+hh] = s0; g_ad[(row0+r0)*4+hh] = d0; }
        if (row0 + r1 < NN) { g_as[(row0+r1)*4+hh] = s1; g_ad[(row0+r1)*4+hh] = d1; }
    }
}

// ---------------- graph setup (once per call) ----------------
// init deg/cnt + per-block easum partials (no atomics)
__global__ __launch_bounds__(256) void k_init(const float* __restrict__ ea) {
    __shared__ float ss[8];
    int tid = blockIdx.x*256 + threadIdx.x;
    if (tid < NN) g_dc[tid] = make_float2(1.f, 0.f);
    float sum = 0.f;
    for (int i = tid; i < EE; i += 1024*256) sum += ea[i];
    #pragma unroll
    for (int o = 16; o; o >>= 1) sum += __shfl_xor_sync(FULL, sum, o);
    if ((threadIdx.x & 31) == 0) ss[threadIdx.x >> 5] = sum;
    __syncthreads();
    if (threadIdx.x < 8) {
        float v = ss[threadIdx.x];
        #pragma unroll
        for (int o = 4; o; o >>= 1) v += __shfl_xor_sync(0xffu, v, o);
        if (threadIdx.x == 0) g_epart[blockIdx.x] = v;
    }
}
__global__ void k_deg_edge(const int* __restrict__ ei, const float* __restrict__ ew) {
    int e = blockIdx.x*256 + threadIdx.x;
    int d = ei[EE+e];
    red_add_v2(&g_dc[d], ew[e], 1.f);
}
__global__ __launch_bounds__(512) void k_scan1() {
    __shared__ int sm[512];
    int t = threadIdx.x;
    int idx = blockIdx.x*512 + t;
    int c = 0;
    if (idx < NN) {
        float2 dc = g_dc[idx];
        g_dinv[idx] = rsqrtf(dc.x);
        c = (int)dc.y;
    }
    sm[t] = c; __syncthreads();
    #pragma unroll
    for (int off = 1; off < 512; off <<= 1) {
        int v = (t >= off) ? sm[t-off] : 0;
        __syncthreads();
        sm[t] += v;
        __syncthreads();
    }
    if (idx < NN) g_ps[idx] = sm[t];
    if (t == 511) g_blk[blockIdx.x] = sm[511];
}
// parallel exclusive scan of block sums + final easum reduction
__global__ void k_scan2(int nblk) {
    int lane = threadIdx.x;              // 32 threads
    int v[4];
    int base = lane * 4;
    #pragma unroll
    for (int i = 0; i < 4; i++) {
        int idx = base + i;
        v[i] = (idx < nblk) ? g_blk[idx] : 0;
    }
    int local = v[0] + v[1] + v[2] + v[3];
    int scan = local;
    #pragma unroll
    for (int o = 1; o < 32; o <<= 1) {
        int n = __shfl_up_sync(FULL, scan, o);
        if (lane >= o) scan += n;
    }
    int excl = scan - local;
    int run = excl;
    #pragma unroll
    for (int i = 0; i < 4; i++) {
        int idx = base + i;
        if (idx < nblk) g_blkoff[idx] = run;
        run += v[i];
    }
    // easum: reduce 1024 partials
    float s = 0.f;
    for (int i = lane; i < 1024; i += 32) s += g_epart[i];
    #pragma unroll
    for (int o = 16; o; o >>= 1) s += __shfl_xor_sync(FULL, s, o);
    if (lane == 0) g_easum = s;
}
__global__ __launch_bounds__(512) void k_scan3() {
    int idx = blockIdx.x*512 + threadIdx.x;
    if (idx < NN) {
        g_rowptr[idx+1] = g_ps[idx] + g_blkoff[blockIdx.x];
        g_cur[idx] = 0;
        if (idx == 0) g_rowptr[0] = 0;
    }
}
__global__ void k_fill(const int* __restrict__ ei, const float* __restrict__ ew,
                       const float* __restrict__ ea) {
    int e = blockIdx.x*256 + threadIdx.x;
    int s = ei[e], d = ei[EE+e];
    int pos = g_rowptr[d] + atomicAdd(&g_cur[d], 1);
    g_cpk[pos] = make_int2(s, __float_as_int(g_dinv[s] * ew[e] * g_dinv[d]));
    g_cdst[pos] = d;
    g_cea[pos]  = ea[e];
}

// -------- GCN gather + silu + residual + LN (warp per node, half-warp per edge) -----
__global__ __launch_bounds__(256) void k_gcn_ln(
    const float* __restrict__ gb, const float* __restrict__ lg, const float* __restrict__ lb)
{
    int row = blockIdx.x*8 + (threadIdx.x >> 5);
    if (row >= NN) return;
    int lane = threadIdx.x & 31;
    int q = lane & 15, half = lane >> 4;
    int start = g_rowptr[row], end = g_rowptr[row+1];
    float4 acc = make_float4(0.f, 0.f, 0.f, 0.f);
    if (half == 0) {
        float dv = g_dinv[row];
        float ss = dv * dv;
        float4 hv = *(const float4*)&g_h[row*64 + q*4];
        acc.x = hv.x*ss; acc.y = hv.y*ss; acc.z = hv.z*ss; acc.w = hv.w*ss;
    }
    for (int j = start + half; j < end; j += 2) {
        int2 pk = __ldg(&g_cpk[j]);
        float w = __int_as_float(pk.y);
        float4 v = *(const float4*)&g_h[pk.x*64 + q*4];
        acc.x += w*v.x; acc.y += w*v.y; acc.z += w*v.z; acc.w += w*v.w;
    }
    acc.x += __shfl_xor_sync(FULL, acc.x, 16);
    acc.y += __shfl_xor_sync(FULL, acc.y, 16);
    acc.z += __shfl_xor_sync(FULL, acc.z, 16);
    acc.w += __shfl_xor_sync(FULL, acc.w, 16);
    // both halves now hold the full sums; compute LN redundantly, half 0 stores
    float4 gb4 = *(const float4*)&gb[q*4];
    float4 rs4 = *(const float4*)&g_res[row*64 + q*4];
    float4 v;
    v.x = siluf(acc.x + gb4.x) + rs4.x;
    v.y = siluf(acc.y + gb4.y) + rs4.y;
    v.z = siluf(acc.z + gb4.z) + rs4.z;
    v.w = siluf(acc.w + gb4.w) + rs4.w;
    float sum = v.x + v.y + v.z + v.w;
    #pragma unroll
    for (int o = 8; o; o >>= 1) sum += __shfl_xor_sync(FULL, sum, o);
    float mu = sum * (1.f/64.f);
    float4 d;
    d.x = v.x - mu; d.y = v.y - mu; d.z = v.z - mu; d.w = v.w - mu;
    float vs = d.x*d.x + d.y*d.y + d.z*d.z + d.w*d.w;
    #pragma unroll
    for (int o = 8; o; o >>= 1) vs += __shfl_xor_sync(FULL, vs, o);
    float inv = rsqrtf(vs * (1.f/64.f) + 1e-5f);
    if (half == 0) {
        float4 lg4 = *(const float4*)&lg[q*4];
        float4 lb4 = *(const float4*)&lb[q*4];
        float4 o4;
        o4.x = d.x*inv*lg4.x + lb4.x;
        o4.y = d.y*inv*lg4.y + lb4.y;
        o4.z = d.z*inv*lg4.z + lb4.z;
        o4.w = d.w*inv*lg4.w + lb4.w;
        *(float4*)&g_xln[row*64 + q*4] = o4;
    }
}

// ---------------- GAT ----------------
// per-block ce computation into shared: sce[0..3] = ce per head, sce[4] = mean(ea)
__device__ __forceinline__ void block_ce(
    const float* __restrict__ eww, const float* __restrict__ ae, float* sce)
{
    if (threadIdx.x < 32) {
        int lane = threadIdx.x;
        float p0 = eww[lane]*ae[lane];
        float p1 = eww[lane+32]*ae[lane+32];
        #pragma unroll
        for (int o = 8; o; o >>= 1) {
            p0 += __shfl_xor_sync(FULL, p0, o);
            p1 += __shfl_xor_sync(FULL, p1, o);
        }
        if ((lane & 15) == 0) {
            sce[lane >> 4]       = p0;
            sce[2 + (lane >> 4)] = p1;
        }
        if (lane == 0) sce[4] = g_easum * (1.f / EE);
    }
    __syncthreads();
}
// CSR-ordered edge-parallel: exp(alpha) written linearly
__global__ __launch_bounds__(256) void k_gatA(
    const float* __restrict__ eww, const float* __restrict__ aev)
{
    __shared__ float sce[5];
    block_ce(eww, aev, sce);
    int e = blockIdx.x*256 + threadIdx.x;   // CSR slot
    int s = g_cpk[e].x, d = g_cdst[e];
    float eav = g_cea[e];
    float4 av = *(const float4*)&g_as[s*4];
    float4 dv = *(const float4*)&g_ad[d*4];
    float4 ce = *(const float4*)&sce[0];
    float4 p;
    p.x = __expf(fminf(lrelu(av.x + dv.x + eav*ce.x), 70.f));
    p.y = __expf(fminf(lrelu(av.y + dv.y + eav*ce.y), 70.f));
    p.z = __expf(fminf(lrelu(av.z + dv.z + eav*ce.z), 70.f));
    p.w = __expf(fminf(lrelu(av.w + dv.w + eav*ce.w), 70.f));
    *(float4*)&g_ep[e*4] = p;
}
// warp-per-node, half-warp per edge: gather + inline softmax denom + silu + skip
__global__ __launch_bounds__(256) void k_gat_gather(
    const float* __restrict__ eww, const float* __restrict__ aev,
    const float* __restrict__ bg, float* __restrict__ xout)
{
    __shared__ float sce[5];
    block_ce(eww, aev, sce);
    int row = blockIdx.x*8 + (threadIdx.x >> 5);
    if (row >= NN) return;
    int lane = threadIdx.x & 31;
    int q = lane & 15, half = lane >> 4;
    int h = q >> 2;                          // head of this lane's 4 columns
    int start = g_rowptr[row], end = g_rowptr[row+1];
    // self-loop exp(alpha)
    float4 av = *(const float4*)&g_as[row*4];
    float4 dv = *(const float4*)&g_ad[row*4];
    float4 ce = *(const float4*)&sce[0];
    float cm = sce[4];
    float4 ps;
    ps.x = __expf(fminf(lrelu(av.x + dv.x + cm*ce.x), 70.f));
    ps.y = __expf(fminf(lrelu(av.y + dv.y + cm*ce.y), 70.f));
    ps.z = __expf(fminf(lrelu(av.z + dv.z + cm*ce.z), 70.f));
    ps.w = __expf(fminf(lrelu(av.w + dv.w + cm*ce.w), 70.f));
    float p_self = (q < 8) ? ((q < 4) ? ps.x : ps.y) : ((q < 12) ? ps.z : ps.w);
    float4 acc = make_float4(0.f, 0.f, 0.f, 0.f);
    float sa = 0.f;
    if (half == 0) {
        float4 xv = *(const float4*)&g_xg[row*64 + q*4];
        acc.x = xv.x*p_self; acc.y = xv.y*p_self; acc.z = xv.z*p_self; acc.w = xv.w*p_self;
        sa = p_self;
    }
    for (int j = start + half; j < end; j += 2) {
        int s = __ldg(&g_cpk[j]).x;
        float p = __ldg(&g_ep[j*4 + h]);
        float4 v = *(const float4*)&g_xg[s*64 + q*4];
        acc.x += p*v.x; acc.y += p*v.y; acc.z += p*v.z; acc.w += p*v.w;
        sa += p;
    }
    acc.x += __shfl_xor_sync(FULL, acc.x, 16);
    acc.y += __shfl_xor_sync(FULL, acc.y, 16);
    acc.z += __shfl_xor_sync(FULL, acc.z, 16);
    acc.w += __shfl_xor_sync(FULL, acc.w, 16);
    sa    += __shfl_xor_sync(FULL, sa, 16);
    if (half == 0) {
        float ia = 1.f / (sa + 1e-16f);
        float4 bg4 = *(const float4*)&bg[q*4];
        float4 xl4 = *(const float4*)&g_xln[row*64 + q*4];
        float* o = xout ? xout : g_xcur;
        float4 o4;
        o4.x = siluf(acc.x*ia + bg4.x) + xl4.x;
        o4.y = siluf(acc.y*ia + bg4.y) + xl4.y;
        o4.z = siluf(acc.z*ia + bg4.z) + xl4.z;
        o4.w = siluf(acc.w*ia + bg4.w) + xl4.w;
        *(float4*)&o[row*64 + q*4] = o4;
    }
}

// ---------------- launch ----------------
extern "C" void kernel_launch(void* const* d_in, const int* in_sizes, int n_in,
                              void* d_out, int out_size) {
    (void)in_sizes; (void)n_in; (void)out_size;
    const float* x  = (const float*)d_in[0];
    const int*   ei = (const int*)  d_in[1];
    const float* ew = (const float*)d_in[2];
    const float* ea = (const float*)d_in[3];

    // graph-structure setup (layer-independent)
    k_init<<<1024,256>>>(ea);
    k_deg_edge<<<3125,256>>>(ei, ew);
    k_scan1<<<98,512>>>();
    k_scan2<<<1,32>>>(98);
    k_scan3<<<98,512>>>();
    k_fill<<<3125,256>>>(ei, ew, ea);

    for (int L = 0; L < 2; L++) {
        const float* gw  = (const float*)d_in[4+12*L+0];
        const float* gb  = (const float*)d_in[4+12*L+1];
        const float* rw  = (const float*)d_in[4+12*L+2];
        const float* rb  = (const float*)d_in[4+12*L+3];
        const float* lg  = (const float*)d_in[4+12*L+4];
        const float* lb  = (const float*)d_in[4+12*L+5];
        const float* Wg  = (const float*)d_in[4+12*L+6];
        const float* bg  = (const float*)d_in[4+12*L+7];
        const float* asv = (const float*)d_in[4+12*L+8];
        const float* adv = (const float*)d_in[4+12*L+9];
        const float* aev = (const float*)d_in[4+12*L+10];
        const float* eww = (const float*)d_in[4+12*L+11];

        const float* xin  = (L == 0) ? x : nullptr;             // null -> g_xcur
        float*       xout = (L == 1) ? (float*)d_out : nullptr; // null -> g_xcur

        k_gemm_dual<<<1563,256>>>(xin, gw, rw, rb);
        k_gcn_ln<<<6250,256>>>(gb, lg, lb);
        k_gemm_gat<<<782,256>>>(Wg, asv, adv);
        k_gatA<<<3125,256>>>(eww, aev);
        k_gat_gather<<<6250,256>>>(eww, aev, bg, xout);
    }
}

// round 15
// speedup vs baseline: 1.2158x; 1.0290x over previous
#include <cuda_runtime.h>

#define NN 50000
#define EE 800000
#define FULL 0xffffffffu

// ---------------- scratch (static device globals; no allocs) ----------------
static __device__ float  g_h[NN*64];      // GCN-transformed features
static __device__ float  g_res[NN*64];    // residual branch
static __device__ float  g_xln[NN*64];    // post-GCN layernorm output
static __device__ float  g_xg[NN*64];     // GAT-transformed features
static __device__ float  g_xcur[NN*64];   // layer-0 output
static __device__ float2 g_dc[NN];        // (deg, cnt) packed
static __device__ float  g_dinv[NN];
static __device__ int    g_ps[NN];        // inclusive scan scratch
static __device__ int    g_blk[128];      // block sums
static __device__ int    g_blkoff[128];
static __device__ int    g_rowptr[NN+1];
static __device__ int    g_cur[NN];
static __device__ int2   g_cpk[EE];       // CSR slot -> (src, gcn-weight bits)
static __device__ int    g_cdst[EE];      // CSR dst node per slot
static __device__ float  g_cea[EE];       // CSR edge_attr per slot
static __device__ float  g_as[NN*4];
static __device__ float  g_ad[NN*4];
static __device__ float  g_ep[EE*4];      // exp(alpha) per CSR slot, 4 heads
static __device__ float  g_epart[1024];   // easum partials
static __device__ float  g_easum;

// ---------------- helpers ----------------
__device__ __forceinline__ float siluf(float v) { return v * (1.f / (1.f + __expf(-v))); }
__device__ __forceinline__ float lrelu(float v) { return v >= 0.f ? v : 0.2f * v; }
__device__ __forceinline__ void red_add_v2(float2* a, float x, float y) {
    asm volatile("red.global.add.v2.f32 [%0], {%1,%2};"
                 :: "l"(a), "f"(x), "f"(y) : "memory");
}

// ---------------- GEMMs ----------------
// g_h = x@W0, g_res = x@W1 + b1. 32-row tile, 256 threads.
__global__ __launch_bounds__(256) void k_gemm_dual(
    const float* __restrict__ xin, const float* __restrict__ W0,
    const float* __restrict__ W1, const float* __restrict__ b1)
{
    const float* x = xin ? xin : g_xcur;
    __shared__ float xs[32*68];
    __shared__ float ws[2][64*68];
    int t = threadIdx.x;
    int row0 = blockIdx.x * 32;
    for (int i = t; i < 4096; i += 256) {
        int k = i >> 6, c = i & 63;
        ws[0][k*68+c] = W0[i];
        ws[1][k*68+c] = W1[i];
    }
    for (int i = t; i < 2048; i += 256) {
        int r = i >> 6, c = i & 63;
        xs[r*68+c] = (row0 + r < NN) ? x[(row0+r)*64 + c] : 0.f;
    }
    __syncthreads();
    int rg = t >> 4, g = t & 15, m = g >> 3, cb = (g & 7) * 8;
    const float* wp = ws[m];
    int r0 = rg*2, r1 = r0 + 1;
    float a0[8], a1[8];
    #pragma unroll
    for (int j = 0; j < 8; j++) { a0[j] = 0.f; a1[j] = 0.f; }
    #pragma unroll 16
    for (int k = 0; k < 64; k++) {
        float xv0 = xs[r0*68+k], xv1 = xs[r1*68+k];
        float w[8];
        *(float4*)&w[0] = *(const float4*)&wp[k*68+cb];
        *(float4*)&w[4] = *(const float4*)&wp[k*68+cb+4];
        #pragma unroll
        for (int j = 0; j < 8; j++) { a0[j] += xv0 * w[j]; a1[j] += xv1 * w[j]; }
    }
    float* y = m ? g_res : g_h;
    if (m) {
        #pragma unroll
        for (int j = 0; j < 8; j++) { float b = b1[cb+j]; a0[j] += b; a1[j] += b; }
    }
    if (row0 + r0 < NN) {
        *(float4*)&y[(row0+r0)*64+cb]   = *(float4*)&a0[0];
        *(float4*)&y[(row0+r0)*64+cb+4] = *(float4*)&a0[4];
    }
    if (row0 + r1 < NN) {
        *(float4*)&y[(row0+r1)*64+cb]   = *(float4*)&a1[0];
        *(float4*)&y[(row0+r1)*64+cb+4] = *(float4*)&a1[4];
    }
}

// g_xg = g_xln @ W ; fused attention dots g_as/g_ad. 64-row tile, 256 threads.
__global__ __launch_bounds__(256) void k_gemm_gat(
    const float* __restrict__ W,
    const float* __restrict__ asrc, const float* __restrict__ adst)
{
    __shared__ float xs[64*68];
    __shared__ float ws[64*68];
    int t = threadIdx.x;
    int row0 = blockIdx.x * 64;
    for (int i = t; i < 4096; i += 256) {
        int k = i >> 6, c = i & 63;
        ws[k*68+c] = W[i];
    }
    for (int i = t; i < 4096; i += 256) {
        int r = i >> 6, c = i & 63;
        xs[r*68+c] = (row0 + r < NN) ? g_xln[(row0+r)*64 + c] : 0.f;
    }
    __syncthreads();
    int rg = t >> 3, cb = (t & 7) * 8;
    int r0 = rg*2, r1 = r0 + 1;
    float a0[8], a1[8];
    #pragma unroll
    for (int j = 0; j < 8; j++) { a0[j] = 0.f; a1[j] = 0.f; }
    #pragma unroll 16
    for (int k = 0; k < 64; k++) {
        float xv0 = xs[r0*68+k], xv1 = xs[r1*68+k];
        float w[8];
        *(float4*)&w[0] = *(const float4*)&ws[k*68+cb];
        *(float4*)&w[4] = *(const float4*)&ws[k*68+cb+4];
        #pragma unroll
        for (int j = 0; j < 8; j++) { a0[j] += xv0 * w[j]; a1[j] += xv1 * w[j]; }
    }
    if (row0 + r0 < NN) {
        *(float4*)&g_xg[(row0+r0)*64+cb]   = *(float4*)&a0[0];
        *(float4*)&g_xg[(row0+r0)*64+cb+4] = *(float4*)&a0[4];
    }
    if (row0 + r1 < NN) {
        *(float4*)&g_xg[(row0+r1)*64+cb]   = *(float4*)&a1[0];
        *(float4*)&g_xg[(row0+r1)*64+cb+4] = *(float4*)&a1[4];
    }
    // fused attention dots: thread pair (t, t^1) covers one head (16 cols)
    float s0 = 0.f, s1 = 0.f, d0 = 0.f, d1 = 0.f;
    #pragma unroll
    for (int j = 0; j < 8; j++) {
        float av = asrc[cb+j], dv = adst[cb+j];
        s0 += a0[j]*av; d0 += a0[j]*dv;
        s1 += a1[j]*av; d1 += a1[j]*dv;
    }
    s0 += __shfl_xor_sync(FULL, s0, 1);
    s1 += __shfl_xor_sync(FULL, s1, 1);
    d0 += __shfl_xor_sync(FULL, d0, 1);
    d1 += __shfl_xor_sync(FULL, d1, 1);
    if ((t & 1) == 0) {
        int hh = cb >> 4;
        if (row0 + r0 < NN) { g_as[(row0+r0)*4+hh] = s0; g_ad[(row0+r0)*4+hh] = d0; }
        if (row0 + r1 < NN) { g_as[(row0+r1)*4+hh] = s1; g_ad[(row0+r1)*4+hh] = d1; }
    }
}

// ---------------- graph setup (once per call) ----------------
// init deg/cnt + per-block easum partials (no atomics)
__global__ __launch_bounds__(256) void k_init(const float* __restrict__ ea) {
    __shared__ float ss[8];
    int tid = blockIdx.x*256 + threadIdx.x;
    if (tid < NN) g_dc[tid] = make_float2(1.f, 0.f);
    float sum = 0.f;
    for (int i = tid; i < EE; i += 1024*256) sum += ea[i];
    #pragma unroll
    for (int o = 16; o; o >>= 1) sum += __shfl_xor_sync(FULL, sum, o);
    if ((threadIdx.x & 31) == 0) ss[threadIdx.x >> 5] = sum;
    __syncthreads();
    if (threadIdx.x < 8) {
        float v = ss[threadIdx.x];
        #pragma unroll
        for (int o = 4; o; o >>= 1) v += __shfl_xor_sync(0xffu, v, o);
        if (threadIdx.x == 0) g_epart[blockIdx.x] = v;
    }
}
__global__ void k_deg_edge(const int* __restrict__ ei, const float* __restrict__ ew) {
    int e = blockIdx.x*256 + threadIdx.x;
    int d = ei[EE+e];
    red_add_v2(&g_dc[d], ew[e], 1.f);
}
__global__ __launch_bounds__(512) void k_scan1() {
    __shared__ int sm[512];
    int t = threadIdx.x;
    int idx = blockIdx.x*512 + t;
    int c = 0;
    if (idx < NN) {
        float2 dc = g_dc[idx];
        g_dinv[idx] = rsqrtf(dc.x);
        c = (int)dc.y;
    }
    sm[t] = c; __syncthreads();
    #pragma unroll
    for (int off = 1; off < 512; off <<= 1) {
        int v = (t >= off) ? sm[t-off] : 0;
        __syncthreads();
        sm[t] += v;
        __syncthreads();
    }
    if (idx < NN) g_ps[idx] = sm[t];
    if (t == 511) g_blk[blockIdx.x] = sm[511];
}
// parallel exclusive scan of block sums + final easum reduction
__global__ void k_scan2(int nblk) {
    int lane = threadIdx.x;              // 32 threads
    int v[4];
    int base = lane * 4;
    #pragma unroll
    for (int i = 0; i < 4; i++) {
        int idx = base + i;
        v[i] = (idx < nblk) ? g_blk[idx] : 0;
    }
    int local = v[0] + v[1] + v[2] + v[3];
    int scan = local;
    #pragma unroll
    for (int o = 1; o < 32; o <<= 1) {
        int n = __shfl_up_sync(FULL, scan, o);
        if (lane >= o) scan += n;
    }
    int excl = scan - local;
    int run = excl;
    #pragma unroll
    for (int i = 0; i < 4; i++) {
        int idx = base + i;
        if (idx < nblk) g_blkoff[idx] = run;
        run += v[i];
    }
    // easum: reduce 1024 partials
    float s = 0.f;
    for (int i = lane; i < 1024; i += 32) s += g_epart[i];
    #pragma unroll
    for (int o = 16; o; o >>= 1) s += __shfl_xor_sync(FULL, s, o);
    if (lane == 0) g_easum = s;
}
__global__ __launch_bounds__(512) void k_scan3() {
    int idx = blockIdx.x*512 + threadIdx.x;
    if (idx < NN) {
        g_rowptr[idx+1] = g_ps[idx] + g_blkoff[blockIdx.x];
        g_cur[idx] = 0;
        if (idx == 0) g_rowptr[0] = 0;
    }
}
__global__ void k_fill(const int* __restrict__ ei, const float* __restrict__ ew,
                       const float* __restrict__ ea) {
    int e = blockIdx.x*256 + threadIdx.x;
    int s = ei[e], d = ei[EE+e];
    int pos = g_rowptr[d] + atomicAdd(&g_cur[d], 1);
    g_cpk[pos] = make_int2(s, __float_as_int(g_dinv[s] * ew[e] * g_dinv[d]));
    g_cdst[pos] = d;
    g_cea[pos]  = ea[e];
}

// -------- GCN gather + silu + residual + LN (warp per node, half-warp per edge) -----
__global__ __launch_bounds__(256) void k_gcn_ln(
    const float* __restrict__ gb, const float* __restrict__ lg, const float* __restrict__ lb)
{
    int row = blockIdx.x*8 + (threadIdx.x >> 5);
    if (row >= NN) return;
    int lane = threadIdx.x & 31;
    int q = lane & 15, half = lane >> 4;
    int start = g_rowptr[row], end = g_rowptr[row+1];
    float4 acc = make_float4(0.f, 0.f, 0.f, 0.f);
    if (half == 0) {
        float dv = g_dinv[row];
        float ss = dv * dv;
        float4 hv = *(const float4*)&g_h[row*64 + q*4];
        acc.x = hv.x*ss; acc.y = hv.y*ss; acc.z = hv.z*ss; acc.w = hv.w*ss;
    }
    for (int j = start + half; j < end; j += 2) {
        int2 pk = __ldg(&g_cpk[j]);
        float w = __int_as_float(pk.y);
        float4 v = *(const float4*)&g_h[pk.x*64 + q*4];
        acc.x += w*v.x; acc.y += w*v.y; acc.z += w*v.z; acc.w += w*v.w;
    }
    acc.x += __shfl_xor_sync(FULL, acc.x, 16);
    acc.y += __shfl_xor_sync(FULL, acc.y, 16);
    acc.z += __shfl_xor_sync(FULL, acc.z, 16);
    acc.w += __shfl_xor_sync(FULL, acc.w, 16);
    // both halves now hold the full sums; compute LN redundantly, half 0 stores
    float4 gb4 = *(const float4*)&gb[q*4];
    float4 rs4 = *(const float4*)&g_res[row*64 + q*4];
    float4 v;
    v.x = siluf(acc.x + gb4.x) + rs4.x;
    v.y = siluf(acc.y + gb4.y) + rs4.y;
    v.z = siluf(acc.z + gb4.z) + rs4.z;
    v.w = siluf(acc.w + gb4.w) + rs4.w;
    float sum = v.x + v.y + v.z + v.w;
    #pragma unroll
    for (int o = 8; o; o >>= 1) sum += __shfl_xor_sync(FULL, sum, o);
    float mu = sum * (1.f/64.f);
    float4 d;
    d.x = v.x - mu; d.y = v.y - mu; d.z = v.z - mu; d.w = v.w - mu;
    float vs = d.x*d.x + d.y*d.y + d.z*d.z + d.w*d.w;
    #pragma unroll
    for (int o = 8; o; o >>= 1) vs += __shfl_xor_sync(FULL, vs, o);
    float inv = rsqrtf(vs * (1.f/64.f) + 1e-5f);
    if (half == 0) {
        float4 lg4 = *(const float4*)&lg[q*4];
        float4 lb4 = *(const float4*)&lb[q*4];
        float4 o4;
        o4.x = d.x*inv*lg4.x + lb4.x;
        o4.y = d.y*inv*lg4.y + lb4.y;
        o4.z = d.z*inv*lg4.z + lb4.z;
        o4.w = d.w*inv*lg4.w + lb4.w;
        *(float4*)&g_xln[row*64 + q*4] = o4;
    }
}

// ---------------- GAT ----------------
// per-block ce computation into shared: sce[0..3] = ce per head, sce[4] = mean(ea)
__device__ __forceinline__ void block_ce(
    const float* __restrict__ eww, const float* __restrict__ ae, float* sce)
{
    if (threadIdx.x < 32) {
        int lane = threadIdx.x;
        float p0 = eww[lane]*ae[lane];
        float p1 = eww[lane+32]*ae[lane+32];
        #pragma unroll
        for (int o = 8; o; o >>= 1) {
            p0 += __shfl_xor_sync(FULL, p0, o);
            p1 += __shfl_xor_sync(FULL, p1, o);
        }
        if ((lane & 15) == 0) {
            sce[lane >> 4]       = p0;
            sce[2 + (lane >> 4)] = p1;
        }
        if (lane == 0) sce[4] = g_easum * (1.f / EE);
    }
    __syncthreads();
}
// CSR-ordered edge-parallel: exp(alpha) written linearly
__global__ __launch_bounds__(256) void k_gatA(
    const float* __restrict__ eww, const float* __restrict__ aev)
{
    __shared__ float sce[5];
    block_ce(eww, aev, sce);
    int e = blockIdx.x*256 + threadIdx.x;   // CSR slot
    int s = g_cpk[e].x, d = g_cdst[e];
    float eav = g_cea[e];
    float4 av = *(const float4*)&g_as[s*4];
    float4 dv = *(const float4*)&g_ad[d*4];
    float4 ce = *(const float4*)&sce[0];
    float4 p;
    p.x = __expf(fminf(lrelu(av.x + dv.x + eav*ce.x), 70.f));
    p.y = __expf(fminf(lrelu(av.y + dv.y + eav*ce.y), 70.f));
    p.z = __expf(fminf(lrelu(av.z + dv.z + eav*ce.z), 70.f));
    p.w = __expf(fminf(lrelu(av.w + dv.w + eav*ce.w), 70.f));
    *(float4*)&g_ep[e*4] = p;
}
// warp-per-node, half-warp per edge: gather + inline softmax denom + silu + skip
__global__ __launch_bounds__(256) void k_gat_gather(
    const float* __restrict__ eww, const float* __restrict__ aev,
    const float* __restrict__ bg, float* __restrict__ xout)
{
    __shared__ float sce[5];
    block_ce(eww, aev, sce);
    int row = blockIdx.x*8 + (threadIdx.x >> 5);
    if (row >= NN) return;
    int lane = threadIdx.x & 31;
    int q = lane & 15, half = lane >> 4;
    int h = q >> 2;                          // head of this lane's 4 columns
    int start = g_rowptr[row], end = g_rowptr[row+1];
    // self-loop exp(alpha)
    float4 av = *(const float4*)&g_as[row*4];
    float4 dv = *(const float4*)&g_ad[row*4];
    float4 ce = *(const float4*)&sce[0];
    float cm = sce[4];
    float4 ps;
    ps.x = __expf(fminf(lrelu(av.x + dv.x + cm*ce.x), 70.f));
    ps.y = __expf(fminf(lrelu(av.y + dv.y + cm*ce.y), 70.f));
    ps.z = __expf(fminf(lrelu(av.z + dv.z + cm*ce.z), 70.f));
    ps.w = __expf(fminf(lrelu(av.w + dv.w + cm*ce.w), 70.f));
    float p_self = (q < 8) ? ((q < 4) ? ps.x : ps.y) : ((q < 12) ? ps.z : ps.w);
    float4 acc = make_float4(0.f, 0.f, 0.f, 0.f);
    float sa = 0.f;
    if (half == 0) {
        float4 xv = *(const float4*)&g_xg[row*64 + q*4];
        acc.x = xv.x*p_self; acc.y = xv.y*p_self; acc.z = xv.z*p_self; acc.w = xv.w*p_self;
        sa = p_self;
    }
    for (int j = start + half; j < end; j += 2) {
        int s = __ldg(&g_cpk[j]).x;
        float p = __ldg(&g_ep[j*4 + h]);
        float4 v = *(const float4*)&g_xg[s*64 + q*4];
        acc.x += p*v.x; acc.y += p*v.y; acc.z += p*v.z; acc.w += p*v.w;
        sa += p;
    }
    acc.x += __shfl_xor_sync(FULL, acc.x, 16);
    acc.y += __shfl_xor_sync(FULL, acc.y, 16);
    acc.z += __shfl_xor_sync(FULL, acc.z, 16);
    acc.w += __shfl_xor_sync(FULL, acc.w, 16);
    sa    += __shfl_xor_sync(FULL, sa, 16);
    if (half == 0) {
        float ia = 1.f / (sa + 1e-16f);
        float4 bg4 = *(const float4*)&bg[q*4];
        float4 xl4 = *(const float4*)&g_xln[row*64 + q*4];
        float* o = xout ? xout : g_xcur;
        float4 o4;
        o4.x = siluf(acc.x*ia + bg4.x) + xl4.x;
        o4.y = siluf(acc.y*ia + bg4.y) + xl4.y;
        o4.z = siluf(acc.z*ia + bg4.z) + xl4.z;
        o4.w = siluf(acc.w*ia + bg4.w) + xl4.w;
        *(float4*)&o[row*64 + q*4] = o4;
    }
}

// ---------------- launch ----------------
extern "C" void kernel_launch(void* const* d_in, const int* in_sizes, int n_in,
                              void* d_out, int out_size) {
    (void)in_sizes; (void)n_in; (void)out_size;
    const float* x  = (const float*)d_in[0];
    const int*   ei = (const int*)  d_in[1];
    const float* ew = (const float*)d_in[2];
    const float* ea = (const float*)d_in[3];

    // fork a side stream for the CSR-setup chain; run layer-0 GEMM concurrently
    cudaStream_t s2;
    cudaStreamCreate(&s2);
    cudaEvent_t evFork, evJoin;
    cudaEventCreateWithFlags(&evFork, cudaEventDisableTiming);
    cudaEventCreateWithFlags(&evJoin, cudaEventDisableTiming);

    cudaEventRecord(evFork, 0);
    cudaStreamWaitEvent(s2, evFork, 0);

    // graph-structure setup (layer-independent) on side stream
    k_init<<<1024,256,0,s2>>>(ea);
    k_deg_edge<<<3125,256,0,s2>>>(ei, ew);
    k_scan1<<<98,512,0,s2>>>();
    k_scan2<<<1,32,0,s2>>>(98);
    k_scan3<<<98,512,0,s2>>>();
    k_fill<<<3125,256,0,s2>>>(ei, ew, ea);
    cudaEventRecord(evJoin, s2);

    // layer-0 GEMM (depends only on x + weights) overlaps setup
    k_gemm_dual<<<1563,256>>>(x, (const float*)d_in[4], (const float*)d_in[6],
                              (const float*)d_in[7]);
    cudaStreamWaitEvent(0, evJoin, 0);

    for (int L = 0; L < 2; L++) {
        const float* gw  = (const float*)d_in[4+12*L+0];
        const float* gb  = (const float*)d_in[4+12*L+1];
        const float* rw  = (const float*)d_in[4+12*L+2];
        const float* rb  = (const float*)d_in[4+12*L+3];
        const float* lg  = (const float*)d_in[4+12*L+4];
        const float* lb  = (const float*)d_in[4+12*L+5];
        const float* Wg  = (const float*)d_in[4+12*L+6];
        const float* bg  = (const float*)d_in[4+12*L+7];
        const float* asv = (const float*)d_in[4+12*L+8];
        const float* adv = (const float*)d_in[4+12*L+9];
        const float* aev = (const float*)d_in[4+12*L+10];
        const float* eww = (const float*)d_in[4+12*L+11];

        float* xout = (L == 1) ? (float*)d_out : nullptr;       // null -> g_xcur

        if (L == 1)
            k_gemm_dual<<<1563,256>>>(nullptr, gw, rw, rb);     // uses g_xcur
        k_gcn_ln<<<6250,256>>>(gb, lg, lb);
        k_gemm_gat<<<782,256>>>(Wg, asv, adv);
        k_gatA<<<3125,256>>>(eww, aev);
        k_gat_gather<<<6250,256>>>(eww, aev, bg, xout);
    }

    cudaEventDestroy(evFork);
    cudaEventDestroy(evJoin);
    cudaStreamDestroy(s2);
}